// round 5
// baseline (speedup 1.0000x reference)
#include <cuda_runtime.h>

#define BB 4
#define SS 1024
#define DDIM 768
#define HH 12
#define EE 8
#define HID 3072
#define DH 64
#define NTOK (BB*SS)
#define CAP (NTOK*2)

// ---------------- scratch (device globals: no allocation allowed) ----------------
__device__ float g_a[NTOK*DDIM];     // ln_attn(x)
__device__ float g_q[NTOK*DDIM];
__device__ float g_k[NTOK*DDIM];
__device__ float g_v[NTOK*DDIM];
__device__ float g_ctx[NTOK*DDIM];
__device__ float g_xa[NTOK*DDIM];    // x + attn_out
__device__ float g_h[NTOK*DDIM];     // ln_ff(xa)
__device__ float g_y1[CAP*HID];      // expert hidden (per token-slot pair)
__device__ float g_o2[CAP*DDIM];     // expert out (per pair)
__device__ float g_sc[CAP];          // top-2 softmax weights (per pair)
__device__ int   g_cnt[EE];
__device__ int   g_list[EE*CAP];

// ---------------- helpers ----------------
__device__ __forceinline__ unsigned f2tf32(float x) {
    unsigned u; asm("cvt.rna.tf32.f32 %0, %1;" : "=r"(u) : "f"(x)); return u;
}

__device__ __forceinline__ void mma_tf32(float c[4], const unsigned a[4], const unsigned b[2]) {
    asm volatile("mma.sync.aligned.m16n8k8.row.col.f32.tf32.tf32.f32 "
        "{%0,%1,%2,%3}, {%4,%5,%6,%7}, {%8,%9}, {%0,%1,%2,%3};"
        : "+f"(c[0]), "+f"(c[1]), "+f"(c[2]), "+f"(c[3])
        : "r"(a[0]), "r"(a[1]), "r"(a[2]), "r"(a[3]), "r"(b[0]), "r"(b[1]));
}

__device__ __forceinline__ float blockReduceSum(float v) {
    __shared__ float sh[33];
    __syncthreads();
    int lane = threadIdx.x & 31, wid = threadIdx.x >> 5;
    #pragma unroll
    for (int o = 16; o > 0; o >>= 1) v += __shfl_down_sync(0xffffffffu, v, o);
    if (lane == 0) sh[wid] = v;
    __syncthreads();
    float r = (threadIdx.x < (blockDim.x >> 5)) ? sh[threadIdx.x] : 0.f;
    if (wid == 0) {
        #pragma unroll
        for (int o = 16; o > 0; o >>= 1) r += __shfl_down_sync(0xffffffffu, r, o);
        if (lane == 0) sh[32] = r;
    }
    __syncthreads();
    return sh[32];
}

// ---------------- layernorm ----------------
__global__ void ln_kernel(const float* __restrict__ x, const float* __restrict__ g,
                          const float* __restrict__ b, float* __restrict__ out) {
    int row = blockIdx.x;
    const float* xr = x + (size_t)row * DDIM;
    float v[3];
    float s = 0.f;
    #pragma unroll
    for (int i = 0; i < 3; i++) { v[i] = xr[threadIdx.x + i*256]; s += v[i]; }
    s = blockReduceSum(s);
    float mean = s * (1.f / DDIM);
    float vs = 0.f;
    #pragma unroll
    for (int i = 0; i < 3; i++) { float d = v[i] - mean; vs += d*d; }
    vs = blockReduceSum(vs);
    float rstd = rsqrtf(vs * (1.f / DDIM) + 1e-5f);
    #pragma unroll
    for (int i = 0; i < 3; i++) {
        int d = threadIdx.x + i*256;
        out[(size_t)row*DDIM + d] = (v[i] - mean) * rstd * g[d] + b[d];
    }
}

// ---------------- TF32 tensor-core GEMM ----------------
// 128x128 block tile, BK=16, 8 warps (4 along M x 2 along N), warp tile 32x64.
// A: [M][K] row-major (optionally gathered rows). B: [K][N] row-major.
// Shared: As[m][k] pad 20, Bs[k][n] pad 136 (conflict-free fragment loads).
template<bool GATHER, bool AROW_PAIR, bool RELU, bool RESID>
__global__ __launch_bounds__(256, 2) void tgemm_k(
    int M, int N, int K,
    const float* __restrict__ A, int lda,
    const float* __restrict__ Bm,
    const float* __restrict__ bias,
    const float* __restrict__ resid,
    float* __restrict__ C, int ldc,
    const int* __restrict__ rowlist,
    const int* __restrict__ cnt)
{
    __shared__ unsigned As[2][128*20];
    __shared__ unsigned Bs[2][16*136];
    __shared__ int rowsS[128];

    if (GATHER) {
        int e = blockIdx.z;
        Bm      += (size_t)e * K * N;
        bias    += (size_t)e * N;
        rowlist += (size_t)e * CAP;
        cnt     += e;
    }
    int m0 = blockIdx.y * 128, n0 = blockIdx.x * 128;
    int tid = threadIdx.x, lane = tid & 31, wid = tid >> 5;
    int warpM = wid & 3, warpN = wid >> 2;

    if (GATHER) {
        int Meff = *cnt;
        if (m0 >= Meff) return;
        if (tid < 128) {
            int gidx = m0 + tid;
            rowsS[tid] = (gidx < Meff) ? rowlist[gidx] : -1;
        }
        __syncthreads();
    }

    // A loader: one thread loads 8 consecutive k of one row: m = tid>>1, kb = (tid&1)*8
    int lm  = tid >> 1;
    int lkb = (tid & 1) << 3;
    const float* Aptr;
    if (GATHER) {
        int pr = rowsS[lm];
        Aptr = (pr < 0) ? nullptr
                        : A + (size_t)(AROW_PAIR ? pr : (pr >> 1)) * lda + lkb;
    } else {
        Aptr = A + (size_t)(m0 + lm) * lda + lkb;
    }
    // B loader: k = tid>>5 (and +8), n = (tid&31)*4
    int lbk = tid >> 5;
    int lbn = (tid & 31) << 2;
    const float* Bptr = Bm + (size_t)lbk * N + n0 + lbn;

    float acc[2][8][4];
    #pragma unroll
    for (int i = 0; i < 2; i++)
        #pragma unroll
        for (int j = 0; j < 8; j++)
            #pragma unroll
            for (int q = 0; q < 4; q++) acc[i][j][q] = 0.f;

    float4 ra0, ra1, rb0, rb1;

    auto loadg = [&](int k0) {
        if (Aptr) {
            ra0 = *(const float4*)(Aptr + k0);
            ra1 = *(const float4*)(Aptr + k0 + 4);
        } else {
            ra0 = make_float4(0,0,0,0); ra1 = ra0;
        }
        rb0 = *(const float4*)(Bptr + (size_t)k0 * N);
        rb1 = *(const float4*)(Bptr + (size_t)(k0 + 8) * N);
    };
    auto stores = [&](int buf) {
        unsigned* ap = &As[buf][lm*20 + lkb];
        ap[0]=f2tf32(ra0.x); ap[1]=f2tf32(ra0.y); ap[2]=f2tf32(ra0.z); ap[3]=f2tf32(ra0.w);
        ap[4]=f2tf32(ra1.x); ap[5]=f2tf32(ra1.y); ap[6]=f2tf32(ra1.z); ap[7]=f2tf32(ra1.w);
        unsigned* bp0 = &Bs[buf][lbk*136 + lbn];
        bp0[0]=f2tf32(rb0.x); bp0[1]=f2tf32(rb0.y); bp0[2]=f2tf32(rb0.z); bp0[3]=f2tf32(rb0.w);
        unsigned* bp1 = &Bs[buf][(lbk+8)*136 + lbn];
        bp1[0]=f2tf32(rb1.x); bp1[1]=f2tf32(rb1.y); bp1[2]=f2tf32(rb1.z); bp1[3]=f2tf32(rb1.w);
    };
    auto compute = [&](int buf) {
        const unsigned* Asb = As[buf];
        const unsigned* Bsb = Bs[buf];
        #pragma unroll
        for (int kk = 0; kk < 16; kk += 8) {
            int kc = kk + (lane & 3);
            unsigned af[2][4];
            #pragma unroll
            for (int mt = 0; mt < 2; mt++) {
                int r = warpM*32 + mt*16 + (lane >> 2);
                af[mt][0] = Asb[r*20 + kc];
                af[mt][1] = Asb[(r+8)*20 + kc];
                af[mt][2] = Asb[r*20 + kc + 4];
                af[mt][3] = Asb[(r+8)*20 + kc + 4];
            }
            unsigned bf[8][2];
            #pragma unroll
            for (int nt = 0; nt < 8; nt++) {
                int c = warpN*64 + nt*8 + (lane >> 2);
                bf[nt][0] = Bsb[kc*136 + c];
                bf[nt][1] = Bsb[(kc+4)*136 + c];
            }
            #pragma unroll
            for (int mt = 0; mt < 2; mt++)
                #pragma unroll
                for (int nt = 0; nt < 8; nt++)
                    mma_tf32(acc[mt][nt], af[mt], bf[nt]);
        }
    };

    loadg(0);
    stores(0);
    __syncthreads();
    int buf = 0;
    for (int k0 = 0; k0 < K; k0 += 16) {
        bool more = (k0 + 16) < K;
        if (more) loadg(k0 + 16);
        compute(buf);
        if (more) {
            stores(buf ^ 1);
            __syncthreads();
            buf ^= 1;
        }
    }

    // epilogue
    #pragma unroll
    for (int mt = 0; mt < 2; mt++) {
        int rr0 = warpM*32 + mt*16 + (lane >> 2);
        #pragma unroll
        for (int half = 0; half < 2; half++) {
            int rloc = rr0 + half*8;
            int crow;
            if (GATHER) {
                int pr = rowsS[rloc];
                if (pr < 0) continue;
                crow = pr;
            } else {
                crow = m0 + rloc;
            }
            #pragma unroll
            for (int nt = 0; nt < 8; nt++) {
                int col = n0 + warpN*64 + nt*8 + (lane & 3)*2;
                float v0 = acc[mt][nt][half*2 + 0] + bias[col];
                float v1 = acc[mt][nt][half*2 + 1] + bias[col + 1];
                if (RELU) { v0 = fmaxf(v0, 0.f); v1 = fmaxf(v1, 0.f); }
                if (RESID) {
                    const float* rp = resid + (size_t)crow*ldc + col;
                    v0 += rp[0]; v1 += rp[1];
                }
                *(float2*)(C + (size_t)crow*ldc + col) = make_float2(v0, v1);
            }
        }
    }
}

// ---------------- flash attention (causal), one q-row per thread ----------------
__global__ void __launch_bounds__(128, 1) attn_kernel(
    const float* __restrict__ q, const float* __restrict__ k,
    const float* __restrict__ v, float* __restrict__ ctx)
{
    int qt = blockIdx.x, h = blockIdx.y, b = blockIdx.z;
    int tid = threadIdx.x;
    int qidx = qt * 128 + tid;

    __shared__ float4 ksh[32*16];
    __shared__ float4 vsh[32*16];

    float4 qr[16], acc[16];
    const float4* qp = (const float4*)(q + (size_t)(b*SS + qidx)*DDIM + h*DH);
    #pragma unroll
    for (int j = 0; j < 16; j++) {
        float4 t = qp[j];
        qr[j] = make_float4(t.x*0.125f, t.y*0.125f, t.z*0.125f, t.w*0.125f);
        acc[j] = make_float4(0,0,0,0);
    }
    float m = -3.0e38f, l = 0.f;

    int kend = qt*128 + 128;
    if (kend > SS) kend = SS;
    for (int kt = 0; kt < kend; kt += 32) {
        __syncthreads();
        for (int i = tid; i < 512; i += 128) {
            int r = i >> 4, c = i & 15;
            size_t base = (size_t)(b*SS + kt + r)*DDIM + h*DH;
            ksh[i] = *((const float4*)(k + base) + c);
            vsh[i] = *((const float4*)(v + base) + c);
        }
        __syncthreads();

        float s[32];
        float tm = -3.0e38f;
        #pragma unroll
        for (int kk = 0; kk < 32; kk++) {
            const float4* kr = &ksh[kk*16];
            float d = 0.f;
            #pragma unroll
            for (int j = 0; j < 16; j++) {
                float4 kv = kr[j];
                d += qr[j].x*kv.x + qr[j].y*kv.y + qr[j].z*kv.z + qr[j].w*kv.w;
            }
            s[kk] = (kt + kk <= qidx) ? d : -1e9f;
            tm = fmaxf(tm, s[kk]);
        }
        float nm = fmaxf(m, tm);
        float c = __expf(m - nm);
        l *= c;
        #pragma unroll
        for (int j = 0; j < 16; j++) {
            acc[j].x *= c; acc[j].y *= c; acc[j].z *= c; acc[j].w *= c;
        }
        #pragma unroll
        for (int kk = 0; kk < 32; kk++) {
            float p = __expf(s[kk] - nm);
            l += p;
            const float4* vr = &vsh[kk*16];
            #pragma unroll
            for (int j = 0; j < 16; j++) {
                float4 vv = vr[j];
                acc[j].x += p*vv.x; acc[j].y += p*vv.y;
                acc[j].z += p*vv.z; acc[j].w += p*vv.w;
            }
        }
        m = nm;
    }
    float inv = 1.f / l;
    float4* op = (float4*)(ctx + (size_t)(b*SS + qidx)*DDIM + h*DH);
    #pragma unroll
    for (int j = 0; j < 16; j++)
        op[j] = make_float4(acc[j].x*inv, acc[j].y*inv, acc[j].z*inv, acc[j].w*inv);
}

// ---------------- gate ----------------
__global__ void zero_cnt_kernel(int* cnt) {
    if (threadIdx.x < EE) cnt[threadIdx.x] = 0;
}

__global__ void gate_kernel(const float* __restrict__ h, const float* __restrict__ gw,
                            const float* __restrict__ gb, float* __restrict__ sc,
                            int* __restrict__ cnt, int* __restrict__ list)
{
    int warp = (blockIdx.x * blockDim.x + threadIdx.x) >> 5;
    if (warp >= NTOK) return;
    int lane = threadIdx.x & 31;
    float a[8] = {0,0,0,0,0,0,0,0};
    const float* hr = h + (size_t)warp * DDIM;
    for (int d = lane; d < DDIM; d += 32) {
        float hv = hr[d];
        float4 w0 = *(const float4*)(gw + (size_t)d*EE);
        float4 w1 = *(const float4*)(gw + (size_t)d*EE + 4);
        a[0]+=hv*w0.x; a[1]+=hv*w0.y; a[2]+=hv*w0.z; a[3]+=hv*w0.w;
        a[4]+=hv*w1.x; a[5]+=hv*w1.y; a[6]+=hv*w1.z; a[7]+=hv*w1.w;
    }
    #pragma unroll
    for (int e = 0; e < 8; e++)
        #pragma unroll
        for (int o = 16; o > 0; o >>= 1)
            a[e] += __shfl_down_sync(0xffffffffu, a[e], o);
    if (lane == 0) {
        float lg[8];
        #pragma unroll
        for (int e = 0; e < 8; e++) lg[e] = a[e] + gb[e];
        int i0 = 0; float v0 = lg[0];
        #pragma unroll
        for (int e = 1; e < 8; e++) if (lg[e] > v0) { v0 = lg[e]; i0 = e; }
        int i1 = -1; float v1 = -3.0e38f;
        #pragma unroll
        for (int e = 0; e < 8; e++) if (e != i0 && lg[e] > v1) { v1 = lg[e]; i1 = e; }
        float e1 = __expf(v1 - v0);
        float s0 = 1.f / (1.f + e1);
        float s1 = e1 * s0;
        sc[2*warp]   = s0;
        sc[2*warp+1] = s1;
        int p0 = atomicAdd(&cnt[i0], 1);
        list[(size_t)i0*CAP + p0] = 2*warp;
        int p1 = atomicAdd(&cnt[i1], 1);
        list[(size_t)i1*CAP + p1] = 2*warp + 1;
    }
}

// ---------------- combine ----------------
__global__ void combine_kernel(const float* __restrict__ h, const float* __restrict__ o2,
                               const float* __restrict__ sc, const float* __restrict__ xa,
                               const float* __restrict__ g, const float* __restrict__ b,
                               float* __restrict__ out)
{
    int t = blockIdx.x;
    const float* hr = h + (size_t)t*DDIM;
    const float* r0 = o2 + (size_t)(2*t)*DDIM;
    const float* r1 = o2 + (size_t)(2*t+1)*DDIM;
    float s0 = sc[2*t], s1 = sc[2*t+1];
    float tv[3];
    float s = 0.f;
    #pragma unroll
    for (int i = 0; i < 3; i++) {
        int d = threadIdx.x + i*256;
        tv[i] = hr[d] + s0*r0[d] + s1*r1[d];
        s += tv[i];
    }
    s = blockReduceSum(s);
    float mean = s * (1.f / DDIM);
    float vs = 0.f;
    #pragma unroll
    for (int i = 0; i < 3; i++) { float d = tv[i] - mean; vs += d*d; }
    vs = blockReduceSum(vs);
    float rstd = rsqrtf(vs * (1.f / DDIM) + 1e-5f);
    #pragma unroll
    for (int i = 0; i < 3; i++) {
        int d = threadIdx.x + i*256;
        out[(size_t)t*DDIM + d] = xa[(size_t)t*DDIM + d] + (tv[i] - mean)*rstd*g[d] + b[d];
    }
}

// ---------------- launch ----------------
extern "C" void kernel_launch(void* const* d_in, const int* in_sizes, int n_in,
                              void* d_out, int out_size)
{
    const float* x        = (const float*)d_in[0];
    const float* ln_a_g   = (const float*)d_in[2];
    const float* ln_a_b   = (const float*)d_in[3];
    const float* wq       = (const float*)d_in[4];
    const float* bq       = (const float*)d_in[5];
    const float* wk       = (const float*)d_in[6];
    const float* bk       = (const float*)d_in[7];
    const float* wv       = (const float*)d_in[8];
    const float* bv       = (const float*)d_in[9];
    const float* wo       = (const float*)d_in[10];
    const float* bo       = (const float*)d_in[11];
    const float* ln_f_g   = (const float*)d_in[12];
    const float* ln_f_b   = (const float*)d_in[13];
    const float* gate_w   = (const float*)d_in[14];
    const float* gate_b   = (const float*)d_in[15];
    const float* w1       = (const float*)d_in[16];
    const float* b1       = (const float*)d_in[17];
    const float* w2       = (const float*)d_in[18];
    const float* b2       = (const float*)d_in[19];
    const float* moe_g    = (const float*)d_in[20];
    const float* moe_b    = (const float*)d_in[21];
    float* out = (float*)d_out;

    float *a, *qb, *kb, *vb, *ctx, *xa, *h, *y1, *o2, *sc;
    int *cnt, *list;
    cudaGetSymbolAddress((void**)&a,   g_a);
    cudaGetSymbolAddress((void**)&qb,  g_q);
    cudaGetSymbolAddress((void**)&kb,  g_k);
    cudaGetSymbolAddress((void**)&vb,  g_v);
    cudaGetSymbolAddress((void**)&ctx, g_ctx);
    cudaGetSymbolAddress((void**)&xa,  g_xa);
    cudaGetSymbolAddress((void**)&h,   g_h);
    cudaGetSymbolAddress((void**)&y1,  g_y1);
    cudaGetSymbolAddress((void**)&o2,  g_o2);
    cudaGetSymbolAddress((void**)&sc,  g_sc);
    cudaGetSymbolAddress((void**)&cnt, g_cnt);
    cudaGetSymbolAddress((void**)&list,g_list);

    // 1) a = ln_attn(x)
    ln_kernel<<<NTOK, 256>>>(x, ln_a_g, ln_a_b, a);

    // 2) q,k,v projections (tf32 tensor cores)
    dim3 gQKV(DDIM/128, NTOK/128, 1);
    tgemm_k<false,false,false,false><<<gQKV, 256>>>(NTOK, DDIM, DDIM, a, DDIM, wq, bq, nullptr, qb, DDIM, nullptr, nullptr);
    tgemm_k<false,false,false,false><<<gQKV, 256>>>(NTOK, DDIM, DDIM, a, DDIM, wk, bk, nullptr, kb, DDIM, nullptr, nullptr);
    tgemm_k<false,false,false,false><<<gQKV, 256>>>(NTOK, DDIM, DDIM, a, DDIM, wv, bv, nullptr, vb, DDIM, nullptr, nullptr);

    // 3) flash attention (causal)
    attn_kernel<<<dim3(SS/128, HH, BB), 128>>>(qb, kb, vb, ctx);

    // 4) xa = x + ctx @ wo + bo
    tgemm_k<false,false,false,true><<<gQKV, 256>>>(NTOK, DDIM, DDIM, ctx, DDIM, wo, bo, x, xa, DDIM, nullptr, nullptr);

    // 5) h = ln_ff(xa)
    ln_kernel<<<NTOK, 256>>>(xa, ln_f_g, ln_f_b, h);

    // 6) gate: top-2 per token + per-expert pair lists
    zero_cnt_kernel<<<1, 32>>>(cnt);
    gate_kernel<<<NTOK/8, 256>>>(h, gate_w, gate_b, sc, cnt, list);

    // 7) expert GEMM1: y1[pair] = relu(h[token] @ w1[e] + b1[e])
    tgemm_k<true,false,true,false><<<dim3(HID/128, CAP/128, EE), 256>>>(
        CAP, HID, DDIM, h, DDIM, w1, b1, nullptr, y1, HID, list, cnt);

    // 8) expert GEMM2: o2[pair] = y1[pair] @ w2[e] + b2[e]
    tgemm_k<true,true,false,false><<<dim3(DDIM/128, CAP/128, EE), 256>>>(
        CAP, DDIM, HID, y1, HID, w2, b2, nullptr, o2, DDIM, list, cnt);

    // 9) combine + post-LN + final residual
    combine_kernel<<<NTOK, 256>>>(h, o2, sc, xa, moe_g, moe_b, out);
}

// round 6
// speedup vs baseline: 1.0031x; 1.0031x over previous
#include <cuda_runtime.h>

#define BB 4
#define SS 1024
#define DDIM 768
#define HH 12
#define EE 8
#define HID 3072
#define DH 64
#define NTOK (BB*SS)
#define CAP (NTOK*2)

// ---------------- scratch (device globals: no allocation allowed) ----------------
__device__ float g_a[NTOK*DDIM];     // ln_attn(x)
__device__ float g_q[NTOK*DDIM];
__device__ float g_k[NTOK*DDIM];
__device__ float g_v[NTOK*DDIM];
__device__ float g_ctx[NTOK*DDIM];
__device__ float g_xa[NTOK*DDIM];    // x + attn_out
__device__ float g_h[NTOK*DDIM];     // ln_ff(xa)
__device__ float g_y1[CAP*HID];      // expert hidden (per token-slot pair)
__device__ float g_o2[CAP*DDIM];     // expert out (per pair)
__device__ float g_sc[CAP];          // top-2 softmax weights (per pair)
__device__ int   g_cnt[EE];
__device__ int   g_list[EE*CAP];

// ---------------- helpers ----------------
__device__ __forceinline__ unsigned f2tf32(float x) {
    unsigned u; asm("cvt.rna.tf32.f32 %0, %1;" : "=r"(u) : "f"(x)); return u;
}

__device__ __forceinline__ void mma_tf32(float c[4], const unsigned a[4], const unsigned b[2]) {
    asm volatile("mma.sync.aligned.m16n8k8.row.col.f32.tf32.tf32.f32 "
        "{%0,%1,%2,%3}, {%4,%5,%6,%7}, {%8,%9}, {%0,%1,%2,%3};"
        : "+f"(c[0]), "+f"(c[1]), "+f"(c[2]), "+f"(c[3])
        : "r"(a[0]), "r"(a[1]), "r"(a[2]), "r"(a[3]), "r"(b[0]), "r"(b[1]));
}

__device__ __forceinline__ float blockReduceSum(float v) {
    __shared__ float sh[33];
    __syncthreads();
    int lane = threadIdx.x & 31, wid = threadIdx.x >> 5;
    #pragma unroll
    for (int o = 16; o > 0; o >>= 1) v += __shfl_down_sync(0xffffffffu, v, o);
    if (lane == 0) sh[wid] = v;
    __syncthreads();
    float r = (threadIdx.x < (blockDim.x >> 5)) ? sh[threadIdx.x] : 0.f;
    if (wid == 0) {
        #pragma unroll
        for (int o = 16; o > 0; o >>= 1) r += __shfl_down_sync(0xffffffffu, r, o);
        if (lane == 0) sh[32] = r;
    }
    __syncthreads();
    return sh[32];
}

// ---------------- layernorm ----------------
__global__ void ln_kernel(const float* __restrict__ x, const float* __restrict__ g,
                          const float* __restrict__ b, float* __restrict__ out) {
    int row = blockIdx.x;
    const float* xr = x + (size_t)row * DDIM;
    float v[3];
    float s = 0.f;
    #pragma unroll
    for (int i = 0; i < 3; i++) { v[i] = xr[threadIdx.x + i*256]; s += v[i]; }
    s = blockReduceSum(s);
    float mean = s * (1.f / DDIM);
    float vs = 0.f;
    #pragma unroll
    for (int i = 0; i < 3; i++) { float d = v[i] - mean; vs += d*d; }
    vs = blockReduceSum(vs);
    float rstd = rsqrtf(vs * (1.f / DDIM) + 1e-5f);
    #pragma unroll
    for (int i = 0; i < 3; i++) {
        int d = threadIdx.x + i*256;
        out[(size_t)row*DDIM + d] = (v[i] - mean) * rstd * g[d] + b[d];
    }
}

// ---------------- TF32 tensor-core GEMM ----------------
// 128x128 block tile, BK=16, 8 warps (4 along M x 2 along N), warp tile 32x64.
// A: [M][K] row-major (optionally gathered rows). B: [K][N] row-major.
// Shared: As[m][k] pad 20, Bs[k][n] pad 136 (conflict-free fragment loads).
template<bool GATHER, bool AROW_PAIR, bool RELU, bool RESID>
__global__ __launch_bounds__(256, 2) void tgemm_k(
    int M, int N, int K,
    const float* __restrict__ A, int lda,
    const float* __restrict__ Bm,
    const float* __restrict__ bias,
    const float* __restrict__ resid,
    float* __restrict__ C, int ldc,
    const int* __restrict__ rowlist,
    const int* __restrict__ cnt)
{
    __shared__ unsigned As[2][128*20];
    __shared__ unsigned Bs[2][16*136];
    __shared__ int rowsS[128];

    if (GATHER) {
        int e = blockIdx.z;
        Bm      += (size_t)e * K * N;
        bias    += (size_t)e * N;
        rowlist += (size_t)e * CAP;
        cnt     += e;
    }
    int m0 = blockIdx.y * 128, n0 = blockIdx.x * 128;
    int tid = threadIdx.x, lane = tid & 31, wid = tid >> 5;
    int warpM = wid & 3, warpN = wid >> 2;

    if (GATHER) {
        int Meff = *cnt;
        if (m0 >= Meff) return;
        if (tid < 128) {
            int gidx = m0 + tid;
            rowsS[tid] = (gidx < Meff) ? rowlist[gidx] : -1;
        }
        __syncthreads();
    }

    // A loader: one thread loads 8 consecutive k of one row: m = tid>>1, kb = (tid&1)*8
    int lm  = tid >> 1;
    int lkb = (tid & 1) << 3;
    const float* Aptr;
    if (GATHER) {
        int pr = rowsS[lm];
        Aptr = (pr < 0) ? nullptr
                        : A + (size_t)(AROW_PAIR ? pr : (pr >> 1)) * lda + lkb;
    } else {
        Aptr = A + (size_t)(m0 + lm) * lda + lkb;
    }
    // B loader: k = tid>>5 (and +8), n = (tid&31)*4
    int lbk = tid >> 5;
    int lbn = (tid & 31) << 2;
    const float* Bptr = Bm + (size_t)lbk * N + n0 + lbn;

    float acc[2][8][4];
    #pragma unroll
    for (int i = 0; i < 2; i++)
        #pragma unroll
        for (int j = 0; j < 8; j++)
            #pragma unroll
            for (int q = 0; q < 4; q++) acc[i][j][q] = 0.f;

    float4 ra0, ra1, rb0, rb1;

    auto loadg = [&](int k0) {
        if (Aptr) {
            ra0 = *(const float4*)(Aptr + k0);
            ra1 = *(const float4*)(Aptr + k0 + 4);
        } else {
            ra0 = make_float4(0,0,0,0); ra1 = ra0;
        }
        rb0 = *(const float4*)(Bptr + (size_t)k0 * N);
        rb1 = *(const float4*)(Bptr + (size_t)(k0 + 8) * N);
    };
    auto stores = [&](int buf) {
        unsigned* ap = &As[buf][lm*20 + lkb];
        ap[0]=f2tf32(ra0.x); ap[1]=f2tf32(ra0.y); ap[2]=f2tf32(ra0.z); ap[3]=f2tf32(ra0.w);
        ap[4]=f2tf32(ra1.x); ap[5]=f2tf32(ra1.y); ap[6]=f2tf32(ra1.z); ap[7]=f2tf32(ra1.w);
        unsigned* bp0 = &Bs[buf][lbk*136 + lbn];
        bp0[0]=f2tf32(rb0.x); bp0[1]=f2tf32(rb0.y); bp0[2]=f2tf32(rb0.z); bp0[3]=f2tf32(rb0.w);
        unsigned* bp1 = &Bs[buf][(lbk+8)*136 + lbn];
        bp1[0]=f2tf32(rb1.x); bp1[1]=f2tf32(rb1.y); bp1[2]=f2tf32(rb1.z); bp1[3]=f2tf32(rb1.w);
    };
    auto compute = [&](int buf) {
        const unsigned* Asb = As[buf];
        const unsigned* Bsb = Bs[buf];
        #pragma unroll
        for (int kk = 0; kk < 16; kk += 8) {
            int kc = kk + (lane & 3);
            unsigned af[2][4];
            #pragma unroll
            for (int mt = 0; mt < 2; mt++) {
                int r = warpM*32 + mt*16 + (lane >> 2);
                af[mt][0] = Asb[r*20 + kc];
                af[mt][1] = Asb[(r+8)*20 + kc];
                af[mt][2] = Asb[r*20 + kc + 4];
                af[mt][3] = Asb[(r+8)*20 + kc + 4];
            }
            unsigned bf[8][2];
            #pragma unroll
            for (int nt = 0; nt < 8; nt++) {
                int c = warpN*64 + nt*8 + (lane >> 2);
                bf[nt][0] = Bsb[kc*136 + c];
                bf[nt][1] = Bsb[(kc+4)*136 + c];
            }
            #pragma unroll
            for (int mt = 0; mt < 2; mt++)
                #pragma unroll
                for (int nt = 0; nt < 8; nt++)
                    mma_tf32(acc[mt][nt], af[mt], bf[nt]);
        }
    };

    loadg(0);
    stores(0);
    __syncthreads();
    int buf = 0;
    for (int k0 = 0; k0 < K; k0 += 16) {
        bool more = (k0 + 16) < K;
        if (more) loadg(k0 + 16);
        compute(buf);
        if (more) {
            stores(buf ^ 1);
            __syncthreads();
            buf ^= 1;
        }
    }

    // epilogue
    #pragma unroll
    for (int mt = 0; mt < 2; mt++) {
        int rr0 = warpM*32 + mt*16 + (lane >> 2);
        #pragma unroll
        for (int half = 0; half < 2; half++) {
            int rloc = rr0 + half*8;
            int crow;
            if (GATHER) {
                int pr = rowsS[rloc];
                if (pr < 0) continue;
                crow = pr;
            } else {
                crow = m0 + rloc;
            }
            #pragma unroll
            for (int nt = 0; nt < 8; nt++) {
                int col = n0 + warpN*64 + nt*8 + (lane & 3)*2;
                float v0 = acc[mt][nt][half*2 + 0] + bias[col];
                float v1 = acc[mt][nt][half*2 + 1] + bias[col + 1];
                if (RELU) { v0 = fmaxf(v0, 0.f); v1 = fmaxf(v1, 0.f); }
                if (RESID) {
                    const float* rp = resid + (size_t)crow*ldc + col;
                    v0 += rp[0]; v1 += rp[1];
                }
                *(float2*)(C + (size_t)crow*ldc + col) = make_float2(v0, v1);
            }
        }
    }
}

// ---------------- flash attention (causal), one q-row per thread ----------------
__global__ void __launch_bounds__(128, 1) attn_kernel(
    const float* __restrict__ q, const float* __restrict__ k,
    const float* __restrict__ v, float* __restrict__ ctx)
{
    int qt = blockIdx.x, h = blockIdx.y, b = blockIdx.z;
    int tid = threadIdx.x;
    int qidx = qt * 128 + tid;

    __shared__ float4 ksh[32*16];
    __shared__ float4 vsh[32*16];

    float4 qr[16], acc[16];
    const float4* qp = (const float4*)(q + (size_t)(b*SS + qidx)*DDIM + h*DH);
    #pragma unroll
    for (int j = 0; j < 16; j++) {
        float4 t = qp[j];
        qr[j] = make_float4(t.x*0.125f, t.y*0.125f, t.z*0.125f, t.w*0.125f);
        acc[j] = make_float4(0,0,0,0);
    }
    float m = -3.0e38f, l = 0.f;

    int kend = qt*128 + 128;
    if (kend > SS) kend = SS;
    for (int kt = 0; kt < kend; kt += 32) {
        __syncthreads();
        for (int i = tid; i < 512; i += 128) {
            int r = i >> 4, c = i & 15;
            size_t base = (size_t)(b*SS + kt + r)*DDIM + h*DH;
            ksh[i] = *((const float4*)(k + base) + c);
            vsh[i] = *((const float4*)(v + base) + c);
        }
        __syncthreads();

        float s[32];
        float tm = -3.0e38f;
        #pragma unroll
        for (int kk = 0; kk < 32; kk++) {
            const float4* kr = &ksh[kk*16];
            float d = 0.f;
            #pragma unroll
            for (int j = 0; j < 16; j++) {
                float4 kv = kr[j];
                d += qr[j].x*kv.x + qr[j].y*kv.y + qr[j].z*kv.z + qr[j].w*kv.w;
            }
            s[kk] = (kt + kk <= qidx) ? d : -1e9f;
            tm = fmaxf(tm, s[kk]);
        }
        float nm = fmaxf(m, tm);
        float c = __expf(m - nm);
        l *= c;
        #pragma unroll
        for (int j = 0; j < 16; j++) {
            acc[j].x *= c; acc[j].y *= c; acc[j].z *= c; acc[j].w *= c;
        }
        #pragma unroll
        for (int kk = 0; kk < 32; kk++) {
            float p = __expf(s[kk] - nm);
            l += p;
            const float4* vr = &vsh[kk*16];
            #pragma unroll
            for (int j = 0; j < 16; j++) {
                float4 vv = vr[j];
                acc[j].x += p*vv.x; acc[j].y += p*vv.y;
                acc[j].z += p*vv.z; acc[j].w += p*vv.w;
            }
        }
        m = nm;
    }
    float inv = 1.f / l;
    float4* op = (float4*)(ctx + (size_t)(b*SS + qidx)*DDIM + h*DH);
    #pragma unroll
    for (int j = 0; j < 16; j++)
        op[j] = make_float4(acc[j].x*inv, acc[j].y*inv, acc[j].z*inv, acc[j].w*inv);
}

// ---------------- gate ----------------
__global__ void zero_cnt_kernel(int* cnt) {
    if (threadIdx.x < EE) cnt[threadIdx.x] = 0;
}

__global__ void gate_kernel(const float* __restrict__ h, const float* __restrict__ gw,
                            const float* __restrict__ gb, float* __restrict__ sc,
                            int* __restrict__ cnt, int* __restrict__ list)
{
    int warp = (blockIdx.x * blockDim.x + threadIdx.x) >> 5;
    if (warp >= NTOK) return;
    int lane = threadIdx.x & 31;
    float a[8] = {0,0,0,0,0,0,0,0};
    const float* hr = h + (size_t)warp * DDIM;
    for (int d = lane; d < DDIM; d += 32) {
        float hv = hr[d];
        float4 w0 = *(const float4*)(gw + (size_t)d*EE);
        float4 w1 = *(const float4*)(gw + (size_t)d*EE + 4);
        a[0]+=hv*w0.x; a[1]+=hv*w0.y; a[2]+=hv*w0.z; a[3]+=hv*w0.w;
        a[4]+=hv*w1.x; a[5]+=hv*w1.y; a[6]+=hv*w1.z; a[7]+=hv*w1.w;
    }
    #pragma unroll
    for (int e = 0; e < 8; e++)
        #pragma unroll
        for (int o = 16; o > 0; o >>= 1)
            a[e] += __shfl_down_sync(0xffffffffu, a[e], o);
    if (lane == 0) {
        float lg[8];
        #pragma unroll
        for (int e = 0; e < 8; e++) lg[e] = a[e] + gb[e];
        int i0 = 0; float v0 = lg[0];
        #pragma unroll
        for (int e = 1; e < 8; e++) if (lg[e] > v0) { v0 = lg[e]; i0 = e; }
        int i1 = -1; float v1 = -3.0e38f;
        #pragma unroll
        for (int e = 0; e < 8; e++) if (e != i0 && lg[e] > v1) { v1 = lg[e]; i1 = e; }
        float e1 = __expf(v1 - v0);
        float s0 = 1.f / (1.f + e1);
        float s1 = e1 * s0;
        sc[2*warp]   = s0;
        sc[2*warp+1] = s1;
        int p0 = atomicAdd(&cnt[i0], 1);
        list[(size_t)i0*CAP + p0] = 2*warp;
        int p1 = atomicAdd(&cnt[i1], 1);
        list[(size_t)i1*CAP + p1] = 2*warp + 1;
    }
}

// ---------------- combine ----------------
__global__ void combine_kernel(const float* __restrict__ h, const float* __restrict__ o2,
                               const float* __restrict__ sc, const float* __restrict__ xa,
                               const float* __restrict__ g, const float* __restrict__ b,
                               float* __restrict__ out)
{
    int t = blockIdx.x;
    const float* hr = h + (size_t)t*DDIM;
    const float* r0 = o2 + (size_t)(2*t)*DDIM;
    const float* r1 = o2 + (size_t)(2*t+1)*DDIM;
    float s0 = sc[2*t], s1 = sc[2*t+1];
    float tv[3];
    float s = 0.f;
    #pragma unroll
    for (int i = 0; i < 3; i++) {
        int d = threadIdx.x + i*256;
        tv[i] = hr[d] + s0*r0[d] + s1*r1[d];
        s += tv[i];
    }
    s = blockReduceSum(s);
    float mean = s * (1.f / DDIM);
    float vs = 0.f;
    #pragma unroll
    for (int i = 0; i < 3; i++) { float d = tv[i] - mean; vs += d*d; }
    vs = blockReduceSum(vs);
    float rstd = rsqrtf(vs * (1.f / DDIM) + 1e-5f);
    #pragma unroll
    for (int i = 0; i < 3; i++) {
        int d = threadIdx.x + i*256;
        out[(size_t)t*DDIM + d] = xa[(size_t)t*DDIM + d] + (tv[i] - mean)*rstd*g[d] + b[d];
    }
}

// ---------------- launch ----------------
extern "C" void kernel_launch(void* const* d_in, const int* in_sizes, int n_in,
                              void* d_out, int out_size)
{
    const float* x        = (const float*)d_in[0];
    const float* ln_a_g   = (const float*)d_in[2];
    const float* ln_a_b   = (const float*)d_in[3];
    const float* wq       = (const float*)d_in[4];
    const float* bq       = (const float*)d_in[5];
    const float* wk       = (const float*)d_in[6];
    const float* bk       = (const float*)d_in[7];
    const float* wv       = (const float*)d_in[8];
    const float* bv       = (const float*)d_in[9];
    const float* wo       = (const float*)d_in[10];
    const float* bo       = (const float*)d_in[11];
    const float* ln_f_g   = (const float*)d_in[12];
    const float* ln_f_b   = (const float*)d_in[13];
    const float* gate_w   = (const float*)d_in[14];
    const float* gate_b   = (const float*)d_in[15];
    const float* w1       = (const float*)d_in[16];
    const float* b1       = (const float*)d_in[17];
    const float* w2       = (const float*)d_in[18];
    const float* b2       = (const float*)d_in[19];
    const float* moe_g    = (const float*)d_in[20];
    const float* moe_b    = (const float*)d_in[21];
    float* out = (float*)d_out;

    float *a, *qb, *kb, *vb, *ctx, *xa, *h, *y1, *o2, *sc;
    int *cnt, *list;
    cudaGetSymbolAddress((void**)&a,   g_a);
    cudaGetSymbolAddress((void**)&qb,  g_q);
    cudaGetSymbolAddress((void**)&kb,  g_k);
    cudaGetSymbolAddress((void**)&vb,  g_v);
    cudaGetSymbolAddress((void**)&ctx, g_ctx);
    cudaGetSymbolAddress((void**)&xa,  g_xa);
    cudaGetSymbolAddress((void**)&h,   g_h);
    cudaGetSymbolAddress((void**)&y1,  g_y1);
    cudaGetSymbolAddress((void**)&o2,  g_o2);
    cudaGetSymbolAddress((void**)&sc,  g_sc);
    cudaGetSymbolAddress((void**)&cnt, g_cnt);
    cudaGetSymbolAddress((void**)&list,g_list);

    // 1) a = ln_attn(x)
    ln_kernel<<<NTOK, 256>>>(x, ln_a_g, ln_a_b, a);

    // 2) q,k,v projections (tf32 tensor cores)
    dim3 gQKV(DDIM/128, NTOK/128, 1);
    tgemm_k<false,false,false,false><<<gQKV, 256>>>(NTOK, DDIM, DDIM, a, DDIM, wq, bq, nullptr, qb, DDIM, nullptr, nullptr);
    tgemm_k<false,false,false,false><<<gQKV, 256>>>(NTOK, DDIM, DDIM, a, DDIM, wk, bk, nullptr, kb, DDIM, nullptr, nullptr);
    tgemm_k<false,false,false,false><<<gQKV, 256>>>(NTOK, DDIM, DDIM, a, DDIM, wv, bv, nullptr, vb, DDIM, nullptr, nullptr);

    // 3) flash attention (causal)
    attn_kernel<<<dim3(SS/128, HH, BB), 128>>>(qb, kb, vb, ctx);

    // 4) xa = x + ctx @ wo + bo
    tgemm_k<false,false,false,true><<<gQKV, 256>>>(NTOK, DDIM, DDIM, ctx, DDIM, wo, bo, x, xa, DDIM, nullptr, nullptr);

    // 5) h = ln_ff(xa)
    ln_kernel<<<NTOK, 256>>>(xa, ln_f_g, ln_f_b, h);

    // 6) gate: top-2 per token + per-expert pair lists
    zero_cnt_kernel<<<1, 32>>>(cnt);
    gate_kernel<<<NTOK/8, 256>>>(h, gate_w, gate_b, sc, cnt, list);

    // 7) expert GEMM1: y1[pair] = relu(h[token] @ w1[e] + b1[e])
    tgemm_k<true,false,true,false><<<dim3(HID/128, CAP/128, EE), 256>>>(
        CAP, HID, DDIM, h, DDIM, w1, b1, nullptr, y1, HID, list, cnt);

    // 8) expert GEMM2: o2[pair] = y1[pair] @ w2[e] + b2[e]
    tgemm_k<true,true,false,false><<<dim3(DDIM/128, CAP/128, EE), 256>>>(
        CAP, DDIM, HID, y1, HID, w2, b2, nullptr, o2, DDIM, list, cnt);

    // 9) combine + post-LN + final residual
    combine_kernel<<<NTOK, 256>>>(h, o2, sc, xa, moe_g, moe_b, out);
}

// round 7
// speedup vs baseline: 1.0972x; 1.0938x over previous
#include <cuda_runtime.h>

#define BB 4
#define SS 1024
#define DDIM 768
#define HH 12
#define EE 8
#define HID 3072
#define DH 64
#define NTOK (BB*SS)
#define CAP (NTOK*2)

// ---------------- scratch (device globals: no allocation allowed) ----------------
__device__ float g_a[NTOK*DDIM];     // ln_attn(x), tf32-rounded
__device__ float g_q[NTOK*DDIM];
__device__ float g_k[NTOK*DDIM];
__device__ float g_v[NTOK*DDIM];
__device__ float g_ctx[NTOK*DDIM];   // tf32-rounded
__device__ float g_xa[NTOK*DDIM];    // x + attn_out (full precision)
__device__ float g_h[NTOK*DDIM];     // ln_ff(xa) full precision (gate/combine)
__device__ float g_hr[NTOK*DDIM];    // ln_ff(xa) tf32-rounded (GEMM input)
__device__ float g_y1[CAP*HID];      // expert hidden, tf32-rounded
__device__ float g_o2[CAP*DDIM];     // expert out
__device__ float g_sc[CAP];
__device__ int   g_cnt[EE];
__device__ int   g_list[EE*CAP];

// ---------------- helpers ----------------
__device__ __forceinline__ unsigned f2tf32(float x) {
    unsigned u; asm("cvt.rna.tf32.f32 %0, %1;" : "=r"(u) : "f"(x)); return u;
}
__device__ __forceinline__ float roundtf(float x) {
    return __uint_as_float(f2tf32(x));
}
__device__ __forceinline__ void mma_tf32(float c[4], const unsigned a[4], const unsigned b[2]) {
    asm volatile("mma.sync.aligned.m16n8k8.row.col.f32.tf32.tf32.f32 "
        "{%0,%1,%2,%3}, {%4,%5,%6,%7}, {%8,%9}, {%0,%1,%2,%3};"
        : "+f"(c[0]), "+f"(c[1]), "+f"(c[2]), "+f"(c[3])
        : "r"(a[0]), "r"(a[1]), "r"(a[2]), "r"(a[3]), "r"(b[0]), "r"(b[1]));
}
__device__ __forceinline__ unsigned smem_u32(const void* p) {
    return (unsigned)__cvta_generic_to_shared(p);
}
__device__ __forceinline__ void cp_async16(unsigned dst, const float* src, int srcsize) {
    asm volatile("cp.async.cg.shared.global [%0], [%1], 16, %2;"
                 :: "r"(dst), "l"(src), "r"(srcsize));
}
__device__ __forceinline__ void cp_commit() { asm volatile("cp.async.commit_group;"); }
__device__ __forceinline__ void cp_wait0()  { asm volatile("cp.async.wait_group 0;"); }

__device__ __forceinline__ float blockReduceSum(float v) {
    __shared__ float sh[33];
    __syncthreads();
    int lane = threadIdx.x & 31, wid = threadIdx.x >> 5;
    #pragma unroll
    for (int o = 16; o > 0; o >>= 1) v += __shfl_down_sync(0xffffffffu, v, o);
    if (lane == 0) sh[wid] = v;
    __syncthreads();
    float r = (threadIdx.x < (blockDim.x >> 5)) ? sh[threadIdx.x] : 0.f;
    if (wid == 0) {
        #pragma unroll
        for (int o = 16; o > 0; o >>= 1) r += __shfl_down_sync(0xffffffffu, r, o);
        if (lane == 0) sh[32] = r;
    }
    __syncthreads();
    return sh[32];
}

// ---------------- layernorm ----------------
// MODE: 0 = exact only, 1 = tf32-rounded only, 2 = both (out exact, out_r rounded)
template<int MODE>
__global__ void ln_kernel(const float* __restrict__ x, const float* __restrict__ g,
                          const float* __restrict__ b, float* __restrict__ out,
                          float* __restrict__ out_r) {
    int row = blockIdx.x;
    const float* xr = x + (size_t)row * DDIM;
    float v[3];
    float s = 0.f;
    #pragma unroll
    for (int i = 0; i < 3; i++) { v[i] = xr[threadIdx.x + i*256]; s += v[i]; }
    s = blockReduceSum(s);
    float mean = s * (1.f / DDIM);
    float vs = 0.f;
    #pragma unroll
    for (int i = 0; i < 3; i++) { float d = v[i] - mean; vs += d*d; }
    vs = blockReduceSum(vs);
    float rstd = rsqrtf(vs * (1.f / DDIM) + 1e-5f);
    #pragma unroll
    for (int i = 0; i < 3; i++) {
        int d = threadIdx.x + i*256;
        float y = (v[i] - mean) * rstd * g[d] + b[d];
        if (MODE == 0) out[(size_t)row*DDIM + d] = y;
        if (MODE == 1) out[(size_t)row*DDIM + d] = roundtf(y);
        if (MODE == 2) {
            out  [(size_t)row*DDIM + d] = y;
            out_r[(size_t)row*DDIM + d] = roundtf(y);
        }
    }
}

// ---------------- TF32 tensor-core GEMM, cp.async A + perm-layout B ----------------
// 128x128 block tile, BK=16, 8 warps (4 M x 2 N), warp tile 32x64.
// A smem: [m][k] stride 20, filled by cp.async (A values already tf32-rounded).
// B smem: [k][perm(n)] stride 132, perm(n)=(n&7)*16+(n>>3) -> fragment loads are LDS.128.
template<bool GATHER, bool AROW_PAIR, bool RELU, bool RESID, bool ROUND, bool QKV3>
__global__ __launch_bounds__(256, 2) void tgemm_k(
    int M, int N, int K,
    const float* __restrict__ A, int lda,
    const float* __restrict__ Bm,
    const float* __restrict__ bias,
    const float* __restrict__ resid,
    float* __restrict__ C, int ldc,
    const int* __restrict__ rowlist,
    const int* __restrict__ cnt,
    const float* Bm2, const float* bias2, float* C2,
    const float* Bm3, const float* bias3, float* C3)
{
    __shared__ __align__(16) float    As[2][128*20];
    __shared__ __align__(16) unsigned Bs[2][16*132];
    __shared__ int rowsS[128];

    if (QKV3) {
        int z = blockIdx.z;
        if (z == 1) { Bm = Bm2; bias = bias2; C = C2; }
        else if (z == 2) { Bm = Bm3; bias = bias3; C = C3; }
    }
    if (GATHER) {
        int e = blockIdx.z;
        Bm      += (size_t)e * K * N;
        bias    += (size_t)e * N;
        rowlist += (size_t)e * CAP;
        cnt     += e;
    }
    int m0 = blockIdx.y * 128, n0 = blockIdx.x * 128;
    int tid = threadIdx.x, lane = tid & 31, wid = tid >> 5;
    int warpM = wid & 3, warpN = wid >> 2;

    if (GATHER) {
        int Meff = *cnt;
        if (m0 >= Meff) return;
        if (tid < 128) {
            int gidx = m0 + tid;
            rowsS[tid] = (gidx < Meff) ? rowlist[gidx] : -1;
        }
        __syncthreads();
    }

    // ---- A cp.async setup: thread loads row lm, k chunk lkb..lkb+7 ----
    int lm  = tid >> 1;
    int lkb = (tid & 1) << 3;
    const float* Aptr;
    int asz = 16;
    if (GATHER) {
        int pr = rowsS[lm];
        if (pr < 0) { Aptr = A; asz = 0; }
        else Aptr = A + (size_t)(AROW_PAIR ? pr : (pr >> 1)) * lda + lkb;
    } else {
        Aptr = A + (size_t)(m0 + lm) * lda + lkb;
    }
    unsigned aDst0 = smem_u32(&As[0][lm*20 + lkb]);
    unsigned aDst1 = smem_u32(&As[1][lm*20 + lkb]);

    // ---- B reg staging: thread loads rows lbk, lbk+8, cols lbn..lbn+3 ----
    int lbk = tid >> 5;
    int lbn = (tid & 31) << 2;
    const float* Bptr = Bm + (size_t)lbk * N + n0 + lbn;
    int p[4];
    #pragma unroll
    for (int i = 0; i < 4; i++) {
        int n = lbn + i;
        p[i] = (n & 7) * 16 + (n >> 3);
    }

    float acc[2][8][4];
    #pragma unroll
    for (int i = 0; i < 2; i++)
        #pragma unroll
        for (int j = 0; j < 8; j++)
            #pragma unroll
            for (int q = 0; q < 4; q++) acc[i][j][q] = 0.f;

    float4 rb0, rb1;
    auto loadB = [&](int k0) {
        rb0 = *(const float4*)(Bptr + (size_t)k0 * N);
        rb1 = *(const float4*)(Bptr + (size_t)(k0 + 8) * N);
    };
    auto storeB = [&](int buf) {
        unsigned* r0 = &Bs[buf][lbk*132];
        r0[p[0]] = f2tf32(rb0.x); r0[p[1]] = f2tf32(rb0.y);
        r0[p[2]] = f2tf32(rb0.z); r0[p[3]] = f2tf32(rb0.w);
        unsigned* r1 = &Bs[buf][(lbk+8)*132];
        r1[p[0]] = f2tf32(rb1.x); r1[p[1]] = f2tf32(rb1.y);
        r1[p[2]] = f2tf32(rb1.z); r1[p[3]] = f2tf32(rb1.w);
    };
    auto issueA = [&](int k0, int buf) {
        unsigned d = buf ? aDst1 : aDst0;
        cp_async16(d,      Aptr + k0,     asz);
        cp_async16(d + 16, Aptr + k0 + 4, asz);
        cp_commit();
    };
    auto compute = [&](int buf) {
        const float*    Asb = As[buf];
        const unsigned* Bsb = Bs[buf];
        #pragma unroll
        for (int kk = 0; kk < 16; kk += 8) {
            int kc = kk + (lane & 3);
            unsigned af[2][4];
            #pragma unroll
            for (int mt = 0; mt < 2; mt++) {
                int r = warpM*32 + mt*16 + (lane >> 2);
                af[mt][0] = __float_as_uint(Asb[r*20 + kc]);
                af[mt][1] = __float_as_uint(Asb[(r+8)*20 + kc]);
                af[mt][2] = __float_as_uint(Asb[r*20 + kc + 4]);
                af[mt][3] = __float_as_uint(Asb[(r+8)*20 + kc + 4]);
            }
            int bbase = (lane >> 2)*16 + warpN*8;
            const uint4* q0 = (const uint4*)&Bsb[kc*132 + bbase];
            uint4 t0 = q0[0], t1 = q0[1];
            const uint4* q1 = (const uint4*)&Bsb[(kc+4)*132 + bbase];
            uint4 t2 = q1[0], t3 = q1[1];
            unsigned bf[8][2] = {
                {t0.x, t2.x}, {t0.y, t2.y}, {t0.z, t2.z}, {t0.w, t2.w},
                {t1.x, t3.x}, {t1.y, t3.y}, {t1.z, t3.z}, {t1.w, t3.w}
            };
            #pragma unroll
            for (int mt = 0; mt < 2; mt++)
                #pragma unroll
                for (int nt = 0; nt < 8; nt++)
                    mma_tf32(acc[mt][nt], af[mt], bf[nt]);
        }
    };

    // prologue
    loadB(0);
    issueA(0, 0);
    storeB(0);
    cp_wait0();
    __syncthreads();

    int buf = 0;
    for (int k0 = 0; k0 < K; k0 += 16) {
        bool more = (k0 + 16) < K;
        if (more) {
            loadB(k0 + 16);
            issueA(k0 + 16, buf ^ 1);
        }
        compute(buf);
        if (more) {
            storeB(buf ^ 1);
            cp_wait0();
            __syncthreads();
            buf ^= 1;
        }
    }

    // epilogue
    #pragma unroll
    for (int mt = 0; mt < 2; mt++) {
        int rr0 = warpM*32 + mt*16 + (lane >> 2);
        #pragma unroll
        for (int half = 0; half < 2; half++) {
            int rloc = rr0 + half*8;
            int crow;
            if (GATHER) {
                int pr = rowsS[rloc];
                if (pr < 0) continue;
                crow = pr;
            } else {
                crow = m0 + rloc;
            }
            #pragma unroll
            for (int nt = 0; nt < 8; nt++) {
                int col = n0 + warpN*64 + nt*8 + (lane & 3)*2;
                float v0 = acc[mt][nt][half*2 + 0] + bias[col];
                float v1 = acc[mt][nt][half*2 + 1] + bias[col + 1];
                if (RELU) { v0 = fmaxf(v0, 0.f); v1 = fmaxf(v1, 0.f); }
                if (RESID) {
                    const float* rp = resid + (size_t)crow*ldc + col;
                    v0 += rp[0]; v1 += rp[1];
                }
                if (ROUND) { v0 = roundtf(v0); v1 = roundtf(v1); }
                *(float2*)(C + (size_t)crow*ldc + col) = make_float2(v0, v1);
            }
        }
    }
}

// ---------------- flash attention (causal), one q-row per thread ----------------
__global__ void __launch_bounds__(128, 1) attn_kernel(
    const float* __restrict__ q, const float* __restrict__ k,
    const float* __restrict__ v, float* __restrict__ ctx)
{
    int qt = blockIdx.x, h = blockIdx.y, b = blockIdx.z;
    int tid = threadIdx.x;
    int qidx = qt * 128 + tid;

    __shared__ float4 ksh[32*16];
    __shared__ float4 vsh[32*16];

    float4 qr[16], acc[16];
    const float4* qp = (const float4*)(q + (size_t)(b*SS + qidx)*DDIM + h*DH);
    #pragma unroll
    for (int j = 0; j < 16; j++) {
        float4 t = qp[j];
        qr[j] = make_float4(t.x*0.125f, t.y*0.125f, t.z*0.125f, t.w*0.125f);
        acc[j] = make_float4(0,0,0,0);
    }
    float m = -3.0e38f, l = 0.f;

    int kend = qt*128 + 128;
    if (kend > SS) kend = SS;
    for (int kt = 0; kt < kend; kt += 32) {
        __syncthreads();
        for (int i = tid; i < 512; i += 128) {
            int r = i >> 4, c = i & 15;
            size_t base = (size_t)(b*SS + kt + r)*DDIM + h*DH;
            ksh[i] = *((const float4*)(k + base) + c);
            vsh[i] = *((const float4*)(v + base) + c);
        }
        __syncthreads();

        float s[32];
        float tm = -3.0e38f;
        #pragma unroll
        for (int kk = 0; kk < 32; kk++) {
            const float4* kr = &ksh[kk*16];
            float d = 0.f;
            #pragma unroll
            for (int j = 0; j < 16; j++) {
                float4 kv = kr[j];
                d += qr[j].x*kv.x + qr[j].y*kv.y + qr[j].z*kv.z + qr[j].w*kv.w;
            }
            s[kk] = (kt + kk <= qidx) ? d : -1e9f;
            tm = fmaxf(tm, s[kk]);
        }
        float nm = fmaxf(m, tm);
        float c = __expf(m - nm);
        l *= c;
        #pragma unroll
        for (int j = 0; j < 16; j++) {
            acc[j].x *= c; acc[j].y *= c; acc[j].z *= c; acc[j].w *= c;
        }
        #pragma unroll
        for (int kk = 0; kk < 32; kk++) {
            float p = __expf(s[kk] - nm);
            l += p;
            const float4* vr = &vsh[kk*16];
            #pragma unroll
            for (int j = 0; j < 16; j++) {
                float4 vv = vr[j];
                acc[j].x += p*vv.x; acc[j].y += p*vv.y;
                acc[j].z += p*vv.z; acc[j].w += p*vv.w;
            }
        }
        m = nm;
    }
    float inv = 1.f / l;
    float4* op = (float4*)(ctx + (size_t)(b*SS + qidx)*DDIM + h*DH);
    #pragma unroll
    for (int j = 0; j < 16; j++)
        op[j] = make_float4(roundtf(acc[j].x*inv), roundtf(acc[j].y*inv),
                            roundtf(acc[j].z*inv), roundtf(acc[j].w*inv));
}

// ---------------- gate ----------------
__global__ void zero_cnt_kernel(int* cnt) {
    if (threadIdx.x < EE) cnt[threadIdx.x] = 0;
}

__global__ void gate_kernel(const float* __restrict__ h, const float* __restrict__ gw,
                            const float* __restrict__ gb, float* __restrict__ sc,
                            int* __restrict__ cnt, int* __restrict__ list)
{
    int warp = (blockIdx.x * blockDim.x + threadIdx.x) >> 5;
    if (warp >= NTOK) return;
    int lane = threadIdx.x & 31;
    float a[8] = {0,0,0,0,0,0,0,0};
    const float* hr = h + (size_t)warp * DDIM;
    for (int d = lane; d < DDIM; d += 32) {
        float hv = hr[d];
        float4 w0 = *(const float4*)(gw + (size_t)d*EE);
        float4 w1 = *(const float4*)(gw + (size_t)d*EE + 4);
        a[0]+=hv*w0.x; a[1]+=hv*w0.y; a[2]+=hv*w0.z; a[3]+=hv*w0.w;
        a[4]+=hv*w1.x; a[5]+=hv*w1.y; a[6]+=hv*w1.z; a[7]+=hv*w1.w;
    }
    #pragma unroll
    for (int e = 0; e < 8; e++)
        #pragma unroll
        for (int o = 16; o > 0; o >>= 1)
            a[e] += __shfl_down_sync(0xffffffffu, a[e], o);
    if (lane == 0) {
        float lg[8];
        #pragma unroll
        for (int e = 0; e < 8; e++) lg[e] = a[e] + gb[e];
        int i0 = 0; float v0 = lg[0];
        #pragma unroll
        for (int e = 1; e < 8; e++) if (lg[e] > v0) { v0 = lg[e]; i0 = e; }
        int i1 = -1; float v1 = -3.0e38f;
        #pragma unroll
        for (int e = 0; e < 8; e++) if (e != i0 && lg[e] > v1) { v1 = lg[e]; i1 = e; }
        float e1 = __expf(v1 - v0);
        float s0 = 1.f / (1.f + e1);
        float s1 = e1 * s0;
        sc[2*warp]   = s0;
        sc[2*warp+1] = s1;
        int p0 = atomicAdd(&cnt[i0], 1);
        list[(size_t)i0*CAP + p0] = 2*warp;
        int p1 = atomicAdd(&cnt[i1], 1);
        list[(size_t)i1*CAP + p1] = 2*warp + 1;
    }
}

// ---------------- combine ----------------
__global__ void combine_kernel(const float* __restrict__ h, const float* __restrict__ o2,
                               const float* __restrict__ sc, const float* __restrict__ xa,
                               const float* __restrict__ g, const float* __restrict__ b,
                               float* __restrict__ out)
{
    int t = blockIdx.x;
    const float* hr = h + (size_t)t*DDIM;
    const float* r0 = o2 + (size_t)(2*t)*DDIM;
    const float* r1 = o2 + (size_t)(2*t+1)*DDIM;
    float s0 = sc[2*t], s1 = sc[2*t+1];
    float tv[3];
    float s = 0.f;
    #pragma unroll
    for (int i = 0; i < 3; i++) {
        int d = threadIdx.x + i*256;
        tv[i] = hr[d] + s0*r0[d] + s1*r1[d];
        s += tv[i];
    }
    s = blockReduceSum(s);
    float mean = s * (1.f / DDIM);
    float vs = 0.f;
    #pragma unroll
    for (int i = 0; i < 3; i++) { float d = tv[i] - mean; vs += d*d; }
    vs = blockReduceSum(vs);
    float rstd = rsqrtf(vs * (1.f / DDIM) + 1e-5f);
    #pragma unroll
    for (int i = 0; i < 3; i++) {
        int d = threadIdx.x + i*256;
        out[(size_t)t*DDIM + d] = xa[(size_t)t*DDIM + d] + (tv[i] - mean)*rstd*g[d] + b[d];
    }
}

// ---------------- launch ----------------
extern "C" void kernel_launch(void* const* d_in, const int* in_sizes, int n_in,
                              void* d_out, int out_size)
{
    const float* x        = (const float*)d_in[0];
    const float* ln_a_g   = (const float*)d_in[2];
    const float* ln_a_b   = (const float*)d_in[3];
    const float* wq       = (const float*)d_in[4];
    const float* bq       = (const float*)d_in[5];
    const float* wk       = (const float*)d_in[6];
    const float* bk       = (const float*)d_in[7];
    const float* wv       = (const float*)d_in[8];
    const float* bv       = (const float*)d_in[9];
    const float* wo       = (const float*)d_in[10];
    const float* bo       = (const float*)d_in[11];
    const float* ln_f_g   = (const float*)d_in[12];
    const float* ln_f_b   = (const float*)d_in[13];
    const float* gate_w   = (const float*)d_in[14];
    const float* gate_b   = (const float*)d_in[15];
    const float* w1       = (const float*)d_in[16];
    const float* b1       = (const float*)d_in[17];
    const float* w2       = (const float*)d_in[18];
    const float* b2       = (const float*)d_in[19];
    const float* moe_g    = (const float*)d_in[20];
    const float* moe_b    = (const float*)d_in[21];
    float* out = (float*)d_out;

    float *a, *qb, *kb, *vb, *ctx, *xa, *h, *hr, *y1, *o2, *sc;
    int *cnt, *list;
    cudaGetSymbolAddress((void**)&a,   g_a);
    cudaGetSymbolAddress((void**)&qb,  g_q);
    cudaGetSymbolAddress((void**)&kb,  g_k);
    cudaGetSymbolAddress((void**)&vb,  g_v);
    cudaGetSymbolAddress((void**)&ctx, g_ctx);
    cudaGetSymbolAddress((void**)&xa,  g_xa);
    cudaGetSymbolAddress((void**)&h,   g_h);
    cudaGetSymbolAddress((void**)&hr,  g_hr);
    cudaGetSymbolAddress((void**)&y1,  g_y1);
    cudaGetSymbolAddress((void**)&o2,  g_o2);
    cudaGetSymbolAddress((void**)&sc,  g_sc);
    cudaGetSymbolAddress((void**)&cnt, g_cnt);
    cudaGetSymbolAddress((void**)&list,g_list);

    // 1) a = tf32(ln_attn(x))
    ln_kernel<1><<<NTOK, 256>>>(x, ln_a_g, ln_a_b, a, nullptr);

    // 2) fused q,k,v projections (grid.z selects weight/out)
    dim3 gQKV(DDIM/128, NTOK/128, 3);
    tgemm_k<false,false,false,false,false,true><<<gQKV, 256>>>(
        NTOK, DDIM, DDIM, a, DDIM, wq, bq, nullptr, qb, DDIM, nullptr, nullptr,
        wk, bk, kb, wv, bv, vb);

    // 3) flash attention (causal), ctx tf32-rounded
    attn_kernel<<<dim3(SS/128, HH, BB), 128>>>(qb, kb, vb, ctx);

    // 4) xa = x + ctx @ wo + bo
    dim3 gO(DDIM/128, NTOK/128, 1);
    tgemm_k<false,false,false,true,false,false><<<gO, 256>>>(
        NTOK, DDIM, DDIM, ctx, DDIM, wo, bo, x, xa, DDIM, nullptr, nullptr,
        nullptr, nullptr, nullptr, nullptr, nullptr, nullptr);

    // 5) h = ln_ff(xa) (exact) + hr (tf32-rounded)
    ln_kernel<2><<<NTOK, 256>>>(xa, ln_f_g, ln_f_b, h, hr);

    // 6) gate: top-2 per token + per-expert pair lists
    zero_cnt_kernel<<<1, 32>>>(cnt);
    gate_kernel<<<NTOK/8, 256>>>(h, gate_w, gate_b, sc, cnt, list);

    // 7) expert GEMM1: y1[pair] = tf32(relu(hr[token] @ w1[e] + b1[e]))
    tgemm_k<true,false,true,false,true,false><<<dim3(HID/128, CAP/128, EE), 256>>>(
        CAP, HID, DDIM, hr, DDIM, w1, b1, nullptr, y1, HID, list, cnt,
        nullptr, nullptr, nullptr, nullptr, nullptr, nullptr);

    // 8) expert GEMM2: o2[pair] = y1[pair] @ w2[e] + b2[e]
    tgemm_k<true,true,false,false,false,false><<<dim3(DDIM/128, CAP/128, EE), 256>>>(
        CAP, DDIM, HID, y1, HID, w2, b2, nullptr, o2, DDIM, list, cnt,
        nullptr, nullptr, nullptr, nullptr, nullptr, nullptr);

    // 9) combine + post-LN + final residual
    combine_kernel<<<NTOK, 256>>>(h, o2, sc, xa, moe_g, moe_b, out);
}

// round 8
// speedup vs baseline: 1.5083x; 1.3746x over previous
#include <cuda_runtime.h>
#include <cuda_bf16.h>

#define BB 4
#define SS 1024
#define DDIM 768
#define HH 12
#define EE 8
#define HID 3072
#define DH 64
#define NTOK (BB*SS)
#define CAP (NTOK*2)

typedef __nv_bfloat16 bf16;
typedef __nv_bfloat162 bf162;

// ---------------- scratch (device globals: no allocation allowed) ----------------
__device__ bf16  g_a[NTOK*DDIM];     // ln_attn(x), bf16
__device__ float g_q[NTOK*DDIM];
__device__ float g_k[NTOK*DDIM];
__device__ float g_v[NTOK*DDIM];
__device__ bf16  g_ctx[NTOK*DDIM];   // attention out, bf16
__device__ float g_xa[NTOK*DDIM];    // x + attn_out
__device__ float g_h[NTOK*DDIM];     // ln_ff(xa) full precision
__device__ bf16  g_hr[NTOK*DDIM];    // ln_ff(xa) bf16
__device__ bf16  g_y1[CAP*HID];      // expert hidden, bf16
__device__ float g_o2[CAP*DDIM];     // expert out
__device__ float g_sc[CAP];
__device__ int   g_cnt[EE];
__device__ int   g_list[EE*CAP];
// bf16 weight copies
__device__ bf16  g_bwq[DDIM*DDIM];
__device__ bf16  g_bwk[DDIM*DDIM];
__device__ bf16  g_bwv[DDIM*DDIM];
__device__ bf16  g_bwo[DDIM*DDIM];
__device__ bf16  g_bw1[EE*DDIM*HID];
__device__ bf16  g_bw2[EE*HID*DDIM];

// ---------------- helpers ----------------
__device__ __forceinline__ unsigned smem_u32(const void* p) {
    return (unsigned)__cvta_generic_to_shared(p);
}
__device__ __forceinline__ void cp_async16(unsigned dst, const void* src, int srcsize) {
    asm volatile("cp.async.cg.shared.global [%0], [%1], 16, %2;"
                 :: "r"(dst), "l"(src), "r"(srcsize));
}
__device__ __forceinline__ void cp_commit() { asm volatile("cp.async.commit_group;"); }
__device__ __forceinline__ void cp_wait0()  { asm volatile("cp.async.wait_group 0;"); }

__device__ __forceinline__ void ldsm_x4(unsigned* r, unsigned addr) {
    asm volatile("ldmatrix.sync.aligned.m8n8.x4.shared.b16 {%0,%1,%2,%3}, [%4];"
        : "=r"(r[0]), "=r"(r[1]), "=r"(r[2]), "=r"(r[3]) : "r"(addr));
}
__device__ __forceinline__ void ldsm_x4_t(unsigned* r, unsigned addr) {
    asm volatile("ldmatrix.sync.aligned.m8n8.x4.trans.shared.b16 {%0,%1,%2,%3}, [%4];"
        : "=r"(r[0]), "=r"(r[1]), "=r"(r[2]), "=r"(r[3]) : "r"(addr));
}
__device__ __forceinline__ void mma_bf16(float c[4], const unsigned a[4],
                                         unsigned b0, unsigned b1) {
    asm volatile("mma.sync.aligned.m16n8k16.row.col.f32.bf16.bf16.f32 "
        "{%0,%1,%2,%3}, {%4,%5,%6,%7}, {%8,%9}, {%0,%1,%2,%3};"
        : "+f"(c[0]), "+f"(c[1]), "+f"(c[2]), "+f"(c[3])
        : "r"(a[0]), "r"(a[1]), "r"(a[2]), "r"(a[3]), "r"(b0), "r"(b1));
}

__device__ __forceinline__ float blockReduceSum(float v) {
    __shared__ float sh[33];
    __syncthreads();
    int lane = threadIdx.x & 31, wid = threadIdx.x >> 5;
    #pragma unroll
    for (int o = 16; o > 0; o >>= 1) v += __shfl_down_sync(0xffffffffu, v, o);
    if (lane == 0) sh[wid] = v;
    __syncthreads();
    float r = (threadIdx.x < (blockDim.x >> 5)) ? sh[threadIdx.x] : 0.f;
    if (wid == 0) {
        #pragma unroll
        for (int o = 16; o > 0; o >>= 1) r += __shfl_down_sync(0xffffffffu, r, o);
        if (lane == 0) sh[32] = r;
    }
    __syncthreads();
    return sh[32];
}

// ---------------- weight conversion f32 -> bf16 ----------------
__global__ void conv_bf16_kernel(const float* __restrict__ src, bf16* __restrict__ dst, int n4) {
    int i = blockIdx.x * blockDim.x + threadIdx.x;
    if (i < n4) {
        float4 v = *(const float4*)(src + (size_t)i*4);
        bf162* d = (bf162*)(dst + (size_t)i*4);
        d[0] = __floats2bfloat162_rn(v.x, v.y);
        d[1] = __floats2bfloat162_rn(v.z, v.w);
    }
}

// ---------------- layernorm ----------------
// MODE 1: bf16 out only. MODE 2: f32 out + bf16 out_b.
template<int MODE>
__global__ void ln_kernel(const float* __restrict__ x, const float* __restrict__ g,
                          const float* __restrict__ b, float* __restrict__ out,
                          bf16* __restrict__ out_b) {
    int row = blockIdx.x;
    const float* xr = x + (size_t)row * DDIM;
    float v[3];
    float s = 0.f;
    #pragma unroll
    for (int i = 0; i < 3; i++) { v[i] = xr[threadIdx.x + i*256]; s += v[i]; }
    s = blockReduceSum(s);
    float mean = s * (1.f / DDIM);
    float vs = 0.f;
    #pragma unroll
    for (int i = 0; i < 3; i++) { float d = v[i] - mean; vs += d*d; }
    vs = blockReduceSum(vs);
    float rstd = rsqrtf(vs * (1.f / DDIM) + 1e-5f);
    #pragma unroll
    for (int i = 0; i < 3; i++) {
        int d = threadIdx.x + i*256;
        float y = (v[i] - mean) * rstd * g[d] + b[d];
        if (MODE == 1) out_b[(size_t)row*DDIM + d] = __float2bfloat16_rn(y);
        if (MODE == 2) {
            out  [(size_t)row*DDIM + d] = y;
            out_b[(size_t)row*DDIM + d] = __float2bfloat16_rn(y);
        }
    }
}

// ---------------- bf16 tensor-core GEMM ----------------
// 128x128 block tile, BK=32, 8 warps (4 M x 2 N), warp tile 32x64.
// A smem: [m][k] bf16, row stride 40 (80B, conflict-free ldmatrix, 16B-aligned).
// B smem: [k][n] bf16, row stride 136 (272B, conflict-free trans ldmatrix).
// Both staged via cp.async (A and B already bf16 in global).
template<bool GATHER, bool AROW_PAIR, bool RELU, bool RESID, bool OUTBF16, bool QKV3>
__global__ __launch_bounds__(256, 2) void bgemm_k(
    int M, int N, int K,
    const bf16* __restrict__ A, int lda,
    const bf16* __restrict__ Bm,
    const float* __restrict__ bias,
    const float* __restrict__ resid,
    float* __restrict__ C, int ldc,
    const int* __restrict__ rowlist,
    const int* __restrict__ cnt,
    const bf16* Bm2, const float* bias2, float* C2,
    const bf16* Bm3, const float* bias3, float* C3)
{
    __shared__ __align__(16) bf16 As[2][128*40];
    __shared__ __align__(16) bf16 Bs[2][32*136];
    __shared__ int rowsS[128];

    if (QKV3) {
        int z = blockIdx.z;
        if (z == 1) { Bm = Bm2; bias = bias2; C = C2; }
        else if (z == 2) { Bm = Bm3; bias = bias3; C = C3; }
    }
    if (GATHER) {
        int e = blockIdx.z;
        Bm      += (size_t)e * K * N;
        bias    += (size_t)e * N;
        rowlist += (size_t)e * CAP;
        cnt     += e;
    }
    int m0 = blockIdx.y * 128, n0 = blockIdx.x * 128;
    int tid = threadIdx.x, lane = tid & 31, wid = tid >> 5;
    int warpM = wid & 3, warpN = wid >> 2;

    if (GATHER) {
        int Meff = *cnt;
        if (m0 >= Meff) return;
        if (tid < 128) {
            int gidx = m0 + tid;
            rowsS[tid] = (gidx < Meff) ? rowlist[gidx] : -1;
        }
        __syncthreads();
    }

    // ---- A staging: thread -> row lm, chunks acb, acb+1 (16B = 8 bf16 each) ----
    int lm  = tid >> 1;
    int acb = (tid & 1) << 1;            // chunk index 0 or 2
    const bf16* Aptr;
    int asz = 16;
    if (GATHER) {
        int pr = rowsS[lm];
        if (pr < 0) { Aptr = A; asz = 0; }
        else Aptr = A + (size_t)(AROW_PAIR ? pr : (pr >> 1)) * lda + acb*8;
    } else {
        Aptr = A + (size_t)(m0 + lm) * lda + acb*8;
    }
    unsigned aD[2];
    aD[0] = smem_u32(&As[0][lm*40]) + acb*16;
    aD[1] = smem_u32(&As[1][lm*40]) + acb*16;

    // ---- B staging: thread -> row lbr (k), chunks bcb, bcb+1 ----
    int lbr = tid >> 3;
    int bcb = (tid & 7) << 1;
    const bf16* Bptr = Bm + (size_t)lbr * N + n0 + bcb*8;
    unsigned bD[2];
    bD[0] = smem_u32(&Bs[0][lbr*136]) + bcb*16;
    bD[1] = smem_u32(&Bs[1][lbr*136]) + bcb*16;

    // ---- ldmatrix addresses ----
    int lane8 = lane & 7, laneH = lane & 8, laneK = (lane & 16) >> 1; // elem offsets
    unsigned aAddr[2][2], bAddr[2][4];
    #pragma unroll
    for (int bf = 0; bf < 2; bf++) {
        #pragma unroll
        for (int mt = 0; mt < 2; mt++) {
            int r = warpM*32 + mt*16 + lane8 + laneH;
            aAddr[bf][mt] = smem_u32(&As[bf][r*40 + laneK]);
        }
        #pragma unroll
        for (int ntp = 0; ntp < 4; ntp++) {
            int kr = lane8 + laneH;
            int nc = warpN*64 + ntp*16 + laneK;
            bAddr[bf][ntp] = smem_u32(&Bs[bf][kr*136 + nc]);
        }
    }

    float acc[2][8][4];
    #pragma unroll
    for (int i = 0; i < 2; i++)
        #pragma unroll
        for (int j = 0; j < 8; j++)
            #pragma unroll
            for (int q = 0; q < 4; q++) acc[i][j][q] = 0.f;

    auto issueStage = [&](int k0, int bf) {
        // A: 128 x 32 bf16
        cp_async16(aD[bf],      Aptr + k0,     asz);
        cp_async16(aD[bf] + 16, Aptr + k0 + 8, asz);
        // B: 32 x 128 bf16
        const bf16* bs = Bptr + (size_t)k0 * N;
        cp_async16(bD[bf],      bs,     16);
        cp_async16(bD[bf] + 16, bs + 8, 16);
        cp_commit();
    };

    issueStage(0, 0);
    int buf = 0;
    for (int k0 = 0; k0 < K; k0 += 32) {
        cp_wait0();
        __syncthreads();
        if (k0 + 32 < K) issueStage(k0 + 32, buf ^ 1);
        // compute on buf
        #pragma unroll
        for (int kk = 0; kk < 32; kk += 16) {
            unsigned af[2][4];
            ldsm_x4(af[0], aAddr[buf][0] + kk*2);
            ldsm_x4(af[1], aAddr[buf][1] + kk*2);
            #pragma unroll
            for (int ntp = 0; ntp < 4; ntp++) {
                unsigned bfr[4];
                ldsm_x4_t(bfr, bAddr[buf][ntp] + kk*272);
                #pragma unroll
                for (int mt = 0; mt < 2; mt++) {
                    mma_bf16(acc[mt][ntp*2+0], af[mt], bfr[0], bfr[1]);
                    mma_bf16(acc[mt][ntp*2+1], af[mt], bfr[2], bfr[3]);
                }
            }
        }
        buf ^= 1;
    }

    // epilogue
    #pragma unroll
    for (int mt = 0; mt < 2; mt++) {
        int rr0 = warpM*32 + mt*16 + (lane >> 2);
        #pragma unroll
        for (int half = 0; half < 2; half++) {
            int rloc = rr0 + half*8;
            int crow;
            if (GATHER) {
                int pr = rowsS[rloc];
                if (pr < 0) continue;
                crow = pr;
            } else {
                crow = m0 + rloc;
            }
            #pragma unroll
            for (int nt = 0; nt < 8; nt++) {
                int col = n0 + warpN*64 + nt*8 + (lane & 3)*2;
                float v0 = acc[mt][nt][half*2 + 0] + bias[col];
                float v1 = acc[mt][nt][half*2 + 1] + bias[col + 1];
                if (RELU) { v0 = fmaxf(v0, 0.f); v1 = fmaxf(v1, 0.f); }
                if (RESID) {
                    const float* rp = resid + (size_t)crow*ldc + col;
                    v0 += rp[0]; v1 += rp[1];
                }
                if (OUTBF16) {
                    *(bf162*)((bf16*)C + (size_t)crow*ldc + col) =
                        __floats2bfloat162_rn(v0, v1);
                } else {
                    *(float2*)(C + (size_t)crow*ldc + col) = make_float2(v0, v1);
                }
            }
        }
    }
}

// ---------------- flash attention (causal), one q-row per thread ----------------
__global__ void __launch_bounds__(128, 1) attn_kernel(
    const float* __restrict__ q, const float* __restrict__ k,
    const float* __restrict__ v, bf16* __restrict__ ctx)
{
    int qt = blockIdx.x, h = blockIdx.y, b = blockIdx.z;
    int tid = threadIdx.x;
    int qidx = qt * 128 + tid;

    __shared__ float4 ksh[32*16];
    __shared__ float4 vsh[32*16];

    float4 qr[16], acc[16];
    const float4* qp = (const float4*)(q + (size_t)(b*SS + qidx)*DDIM + h*DH);
    #pragma unroll
    for (int j = 0; j < 16; j++) {
        float4 t = qp[j];
        qr[j] = make_float4(t.x*0.125f, t.y*0.125f, t.z*0.125f, t.w*0.125f);
        acc[j] = make_float4(0,0,0,0);
    }
    float m = -3.0e38f, l = 0.f;

    int kend = qt*128 + 128;
    if (kend > SS) kend = SS;
    for (int kt = 0; kt < kend; kt += 32) {
        __syncthreads();
        for (int i = tid; i < 512; i += 128) {
            int r = i >> 4, c = i & 15;
            size_t base = (size_t)(b*SS + kt + r)*DDIM + h*DH;
            ksh[i] = *((const float4*)(k + base) + c);
            vsh[i] = *((const float4*)(v + base) + c);
        }
        __syncthreads();

        float s[32];
        float tm = -3.0e38f;
        #pragma unroll
        for (int kk = 0; kk < 32; kk++) {
            const float4* kr = &ksh[kk*16];
            float d = 0.f;
            #pragma unroll
            for (int j = 0; j < 16; j++) {
                float4 kv = kr[j];
                d += qr[j].x*kv.x + qr[j].y*kv.y + qr[j].z*kv.z + qr[j].w*kv.w;
            }
            s[kk] = (kt + kk <= qidx) ? d : -1e9f;
            tm = fmaxf(tm, s[kk]);
        }
        float nm = fmaxf(m, tm);
        float c = __expf(m - nm);
        l *= c;
        #pragma unroll
        for (int j = 0; j < 16; j++) {
            acc[j].x *= c; acc[j].y *= c; acc[j].z *= c; acc[j].w *= c;
        }
        #pragma unroll
        for (int kk = 0; kk < 32; kk++) {
            float p = __expf(s[kk] - nm);
            l += p;
            const float4* vr = &vsh[kk*16];
            #pragma unroll
            for (int j = 0; j < 16; j++) {
                float4 vv = vr[j];
                acc[j].x += p*vv.x; acc[j].y += p*vv.y;
                acc[j].z += p*vv.z; acc[j].w += p*vv.w;
            }
        }
        m = nm;
    }
    float inv = 1.f / l;
    bf162* op = (bf162*)(ctx + (size_t)(b*SS + qidx)*DDIM + h*DH);
    #pragma unroll
    for (int j = 0; j < 16; j++) {
        op[2*j]   = __floats2bfloat162_rn(acc[j].x*inv, acc[j].y*inv);
        op[2*j+1] = __floats2bfloat162_rn(acc[j].z*inv, acc[j].w*inv);
    }
}

// ---------------- gate ----------------
__global__ void zero_cnt_kernel(int* cnt) {
    if (threadIdx.x < EE) cnt[threadIdx.x] = 0;
}

__global__ void gate_kernel(const float* __restrict__ h, const float* __restrict__ gw,
                            const float* __restrict__ gb, float* __restrict__ sc,
                            int* __restrict__ cnt, int* __restrict__ list)
{
    int warp = (blockIdx.x * blockDim.x + threadIdx.x) >> 5;
    if (warp >= NTOK) return;
    int lane = threadIdx.x & 31;
    float a[8] = {0,0,0,0,0,0,0,0};
    const float* hr = h + (size_t)warp * DDIM;
    for (int d = lane; d < DDIM; d += 32) {
        float hv = hr[d];
        float4 w0 = *(const float4*)(gw + (size_t)d*EE);
        float4 w1 = *(const float4*)(gw + (size_t)d*EE + 4);
        a[0]+=hv*w0.x; a[1]+=hv*w0.y; a[2]+=hv*w0.z; a[3]+=hv*w0.w;
        a[4]+=hv*w1.x; a[5]+=hv*w1.y; a[6]+=hv*w1.z; a[7]+=hv*w1.w;
    }
    #pragma unroll
    for (int e = 0; e < 8; e++)
        #pragma unroll
        for (int o = 16; o > 0; o >>= 1)
            a[e] += __shfl_down_sync(0xffffffffu, a[e], o);
    if (lane == 0) {
        float lg[8];
        #pragma unroll
        for (int e = 0; e < 8; e++) lg[e] = a[e] + gb[e];
        int i0 = 0; float v0 = lg[0];
        #pragma unroll
        for (int e = 1; e < 8; e++) if (lg[e] > v0) { v0 = lg[e]; i0 = e; }
        int i1 = -1; float v1 = -3.0e38f;
        #pragma unroll
        for (int e = 0; e < 8; e++) if (e != i0 && lg[e] > v1) { v1 = lg[e]; i1 = e; }
        float e1 = __expf(v1 - v0);
        float s0 = 1.f / (1.f + e1);
        float s1 = e1 * s0;
        sc[2*warp]   = s0;
        sc[2*warp+1] = s1;
        int p0 = atomicAdd(&cnt[i0], 1);
        list[(size_t)i0*CAP + p0] = 2*warp;
        int p1 = atomicAdd(&cnt[i1], 1);
        list[(size_t)i1*CAP + p1] = 2*warp + 1;
    }
}

// ---------------- combine ----------------
__global__ void combine_kernel(const float* __restrict__ h, const float* __restrict__ o2,
                               const float* __restrict__ sc, const float* __restrict__ xa,
                               const float* __restrict__ g, const float* __restrict__ b,
                               float* __restrict__ out)
{
    int t = blockIdx.x;
    const float* hr = h + (size_t)t*DDIM;
    const float* r0 = o2 + (size_t)(2*t)*DDIM;
    const float* r1 = o2 + (size_t)(2*t+1)*DDIM;
    float s0 = sc[2*t], s1 = sc[2*t+1];
    float tv[3];
    float s = 0.f;
    #pragma unroll
    for (int i = 0; i < 3; i++) {
        int d = threadIdx.x + i*256;
        tv[i] = hr[d] + s0*r0[d] + s1*r1[d];
        s += tv[i];
    }
    s = blockReduceSum(s);
    float mean = s * (1.f / DDIM);
    float vs = 0.f;
    #pragma unroll
    for (int i = 0; i < 3; i++) { float d = tv[i] - mean; vs += d*d; }
    vs = blockReduceSum(vs);
    float rstd = rsqrtf(vs * (1.f / DDIM) + 1e-5f);
    #pragma unroll
    for (int i = 0; i < 3; i++) {
        int d = threadIdx.x + i*256;
        out[(size_t)t*DDIM + d] = xa[(size_t)t*DDIM + d] + (tv[i] - mean)*rstd*g[d] + b[d];
    }
}

// ---------------- launch ----------------
extern "C" void kernel_launch(void* const* d_in, const int* in_sizes, int n_in,
                              void* d_out, int out_size)
{
    const float* x        = (const float*)d_in[0];
    const float* ln_a_g   = (const float*)d_in[2];
    const float* ln_a_b   = (const float*)d_in[3];
    const float* wq       = (const float*)d_in[4];
    const float* bq       = (const float*)d_in[5];
    const float* wk       = (const float*)d_in[6];
    const float* bk       = (const float*)d_in[7];
    const float* wv       = (const float*)d_in[8];
    const float* bv       = (const float*)d_in[9];
    const float* wo       = (const float*)d_in[10];
    const float* bo       = (const float*)d_in[11];
    const float* ln_f_g   = (const float*)d_in[12];
    const float* ln_f_b   = (const float*)d_in[13];
    const float* gate_w   = (const float*)d_in[14];
    const float* gate_b   = (const float*)d_in[15];
    const float* w1       = (const float*)d_in[16];
    const float* b1       = (const float*)d_in[17];
    const float* w2       = (const float*)d_in[18];
    const float* b2       = (const float*)d_in[19];
    const float* moe_g    = (const float*)d_in[20];
    const float* moe_b    = (const float*)d_in[21];
    float* out = (float*)d_out;

    bf16 *a, *ctx, *hrb, *y1, *bwq, *bwk, *bwv, *bwo, *bw1, *bw2;
    float *qb, *kb, *vb, *xa, *h, *o2, *sc;
    int *cnt, *list;
    cudaGetSymbolAddress((void**)&a,   g_a);
    cudaGetSymbolAddress((void**)&qb,  g_q);
    cudaGetSymbolAddress((void**)&kb,  g_k);
    cudaGetSymbolAddress((void**)&vb,  g_v);
    cudaGetSymbolAddress((void**)&ctx, g_ctx);
    cudaGetSymbolAddress((void**)&xa,  g_xa);
    cudaGetSymbolAddress((void**)&h,   g_h);
    cudaGetSymbolAddress((void**)&hrb, g_hr);
    cudaGetSymbolAddress((void**)&y1,  g_y1);
    cudaGetSymbolAddress((void**)&o2,  g_o2);
    cudaGetSymbolAddress((void**)&sc,  g_sc);
    cudaGetSymbolAddress((void**)&cnt, g_cnt);
    cudaGetSymbolAddress((void**)&list,g_list);
    cudaGetSymbolAddress((void**)&bwq, g_bwq);
    cudaGetSymbolAddress((void**)&bwk, g_bwk);
    cudaGetSymbolAddress((void**)&bwv, g_bwv);
    cudaGetSymbolAddress((void**)&bwo, g_bwo);
    cudaGetSymbolAddress((void**)&bw1, g_bw1);
    cudaGetSymbolAddress((void**)&bw2, g_bw2);

    // 0) weight conversions f32 -> bf16
    {
        int nqkv4 = DDIM*DDIM/4;
        int gq = (nqkv4 + 255)/256;
        conv_bf16_kernel<<<gq, 256>>>(wq, bwq, nqkv4);
        conv_bf16_kernel<<<gq, 256>>>(wk, bwk, nqkv4);
        conv_bf16_kernel<<<gq, 256>>>(wv, bwv, nqkv4);
        conv_bf16_kernel<<<gq, 256>>>(wo, bwo, nqkv4);
        int nff4 = EE*DDIM*HID/4;
        int gf = (nff4 + 255)/256;
        conv_bf16_kernel<<<gf, 256>>>(w1, bw1, nff4);
        conv_bf16_kernel<<<gf, 256>>>(w2, bw2, nff4);
    }

    // 1) a = bf16(ln_attn(x))
    ln_kernel<1><<<NTOK, 256>>>(x, ln_a_g, ln_a_b, nullptr, a);

    // 2) fused q,k,v projections (grid.z selects weight/out)
    dim3 gQKV(DDIM/128, NTOK/128, 3);
    bgemm_k<false,false,false,false,false,true><<<gQKV, 256>>>(
        NTOK, DDIM, DDIM, a, DDIM, bwq, bq, nullptr, qb, DDIM, nullptr, nullptr,
        bwk, bk, kb, bwv, bv, vb);

    // 3) flash attention (causal), ctx bf16
    attn_kernel<<<dim3(SS/128, HH, BB), 128>>>(qb, kb, vb, ctx);

    // 4) xa = x + ctx @ wo + bo
    dim3 gO(DDIM/128, NTOK/128, 1);
    bgemm_k<false,false,false,true,false,false><<<gO, 256>>>(
        NTOK, DDIM, DDIM, ctx, DDIM, bwo, bo, x, xa, DDIM, nullptr, nullptr,
        nullptr, nullptr, nullptr, nullptr, nullptr, nullptr);

    // 5) h = ln_ff(xa) (f32) + hr (bf16)
    ln_kernel<2><<<NTOK, 256>>>(xa, ln_f_g, ln_f_b, h, hrb);

    // 6) gate: top-2 per token + per-expert pair lists
    zero_cnt_kernel<<<1, 32>>>(cnt);
    gate_kernel<<<NTOK/8, 256>>>(h, gate_w, gate_b, sc, cnt, list);

    // 7) expert GEMM1: y1[pair] = bf16(relu(hr[token] @ w1[e] + b1[e]))
    bgemm_k<true,false,true,false,true,false><<<dim3(HID/128, CAP/128, EE), 256>>>(
        CAP, HID, DDIM, hrb, DDIM, bw1, b1, nullptr, (float*)y1, HID, list, cnt,
        nullptr, nullptr, nullptr, nullptr, nullptr, nullptr);

    // 8) expert GEMM2: o2[pair] = y1[pair] @ w2[e] + b2[e]
    bgemm_k<true,true,false,false,false,false><<<dim3(DDIM/128, CAP/128, EE), 256>>>(
        CAP, DDIM, HID, y1, HID, bw2, b2, nullptr, o2, DDIM, list, cnt,
        nullptr, nullptr, nullptr, nullptr, nullptr, nullptr);

    // 9) combine + post-LN + final residual
    combine_kernel<<<NTOK, 256>>>(h, o2, sc, xa, moe_g, moe_b, out);
}

// round 9
// speedup vs baseline: 1.5768x; 1.0454x over previous
#include <cuda_runtime.h>
#include <cuda_bf16.h>

#define BB 4
#define SS 1024
#define DDIM 768
#define HH 12
#define EE 8
#define HID 3072
#define DH 64
#define NTOK (BB*SS)
#define CAP (NTOK*2)

typedef __nv_bfloat16 bf16;
typedef __nv_bfloat162 bf162;

// ---------------- scratch (device globals: no allocation allowed) ----------------
__device__ bf16  g_a[NTOK*DDIM];     // ln_attn(x), bf16
__device__ float g_q[NTOK*DDIM];
__device__ float g_k[NTOK*DDIM];
__device__ float g_v[NTOK*DDIM];
__device__ bf16  g_ctx[NTOK*DDIM];   // attention out, bf16
__device__ float g_xa[NTOK*DDIM];    // x + attn_out
__device__ float g_h[NTOK*DDIM];     // ln_ff(xa) full precision
__device__ bf16  g_hr[NTOK*DDIM];    // ln_ff(xa) bf16
__device__ bf16  g_y1[CAP*HID];      // expert hidden, bf16
__device__ float g_o2[CAP*DDIM];     // expert out
__device__ float g_sc[CAP];
__device__ int   g_cnt[EE];
__device__ int   g_list[EE*CAP];
// bf16 weight copies
__device__ bf16  g_bwq[DDIM*DDIM];
__device__ bf16  g_bwk[DDIM*DDIM];
__device__ bf16  g_bwv[DDIM*DDIM];
__device__ bf16  g_bwo[DDIM*DDIM];
__device__ bf16  g_bw1[EE*DDIM*HID];
__device__ bf16  g_bw2[EE*HID*DDIM];

// ---------------- helpers ----------------
__device__ __forceinline__ unsigned smem_u32(const void* p) {
    return (unsigned)__cvta_generic_to_shared(p);
}
__device__ __forceinline__ void cp_async16(unsigned dst, const void* src, int srcsize) {
    asm volatile("cp.async.cg.shared.global [%0], [%1], 16, %2;"
                 :: "r"(dst), "l"(src), "r"(srcsize));
}
__device__ __forceinline__ void cp_commit() { asm volatile("cp.async.commit_group;"); }
template<int N>
__device__ __forceinline__ void cp_wait() { asm volatile("cp.async.wait_group %0;" :: "n"(N)); }

__device__ __forceinline__ void ldsm_x4(unsigned* r, unsigned addr) {
    asm volatile("ldmatrix.sync.aligned.m8n8.x4.shared.b16 {%0,%1,%2,%3}, [%4];"
        : "=r"(r[0]), "=r"(r[1]), "=r"(r[2]), "=r"(r[3]) : "r"(addr));
}
__device__ __forceinline__ void ldsm_x4_t(unsigned* r, unsigned addr) {
    asm volatile("ldmatrix.sync.aligned.m8n8.x4.trans.shared.b16 {%0,%1,%2,%3}, [%4];"
        : "=r"(r[0]), "=r"(r[1]), "=r"(r[2]), "=r"(r[3]) : "r"(addr));
}
__device__ __forceinline__ void mma_bf16(float c[4], const unsigned a[4],
                                         unsigned b0, unsigned b1) {
    asm volatile("mma.sync.aligned.m16n8k16.row.col.f32.bf16.bf16.f32 "
        "{%0,%1,%2,%3}, {%4,%5,%6,%7}, {%8,%9}, {%0,%1,%2,%3};"
        : "+f"(c[0]), "+f"(c[1]), "+f"(c[2]), "+f"(c[3])
        : "r"(a[0]), "r"(a[1]), "r"(a[2]), "r"(a[3]), "r"(b0), "r"(b1));
}

__device__ __forceinline__ float blockReduceSum(float v) {
    __shared__ float sh[33];
    __syncthreads();
    int lane = threadIdx.x & 31, wid = threadIdx.x >> 5;
    #pragma unroll
    for (int o = 16; o > 0; o >>= 1) v += __shfl_down_sync(0xffffffffu, v, o);
    if (lane == 0) sh[wid] = v;
    __syncthreads();
    float r = (threadIdx.x < (blockDim.x >> 5)) ? sh[threadIdx.x] : 0.f;
    if (wid == 0) {
        #pragma unroll
        for (int o = 16; o > 0; o >>= 1) r += __shfl_down_sync(0xffffffffu, r, o);
        if (lane == 0) sh[32] = r;
    }
    __syncthreads();
    return sh[32];
}

// ---------------- weight conversion f32 -> bf16 ----------------
__global__ void conv_bf16_kernel(const float* __restrict__ src, bf16* __restrict__ dst, int n4) {
    int i = blockIdx.x * blockDim.x + threadIdx.x;
    if (i < n4) {
        float4 v = *(const float4*)(src + (size_t)i*4);
        bf162* d = (bf162*)(dst + (size_t)i*4);
        d[0] = __floats2bfloat162_rn(v.x, v.y);
        d[1] = __floats2bfloat162_rn(v.z, v.w);
    }
}

// ---------------- layernorm ----------------
// MODE 1: bf16 out only. MODE 2: f32 out + bf16 out_b.
template<int MODE>
__global__ void ln_kernel(const float* __restrict__ x, const float* __restrict__ g,
                          const float* __restrict__ b, float* __restrict__ out,
                          bf16* __restrict__ out_b) {
    int row = blockIdx.x;
    const float* xr = x + (size_t)row * DDIM;
    float v[3];
    float s = 0.f;
    #pragma unroll
    for (int i = 0; i < 3; i++) { v[i] = xr[threadIdx.x + i*256]; s += v[i]; }
    s = blockReduceSum(s);
    float mean = s * (1.f / DDIM);
    float vs = 0.f;
    #pragma unroll
    for (int i = 0; i < 3; i++) { float d = v[i] - mean; vs += d*d; }
    vs = blockReduceSum(vs);
    float rstd = rsqrtf(vs * (1.f / DDIM) + 1e-5f);
    #pragma unroll
    for (int i = 0; i < 3; i++) {
        int d = threadIdx.x + i*256;
        float y = (v[i] - mean) * rstd * g[d] + b[d];
        if (MODE == 1) out_b[(size_t)row*DDIM + d] = __float2bfloat16_rn(y);
        if (MODE == 2) {
            out  [(size_t)row*DDIM + d] = y;
            out_b[(size_t)row*DDIM + d] = __float2bfloat16_rn(y);
        }
    }
}

// ---------------- bf16 tensor-core GEMM, 4-stage cp.async pipeline ----------------
// 128x128 block tile, BK=32, 8 warps (4 M x 2 N), warp tile 32x64.
// A smem: [m][k] bf16 stride 40 (80B rows, conflict-free ldmatrix, 16B aligned).
// B smem: [k][n] bf16 stride 136 (272B rows, conflict-free trans ldmatrix).
// Dynamic smem: 4 stages (A 10240B + B 8704B each) + rowsS.
#define ASTG 5120   /* bf16 elems per A stage (128*40) */
#define BSTG 4352   /* bf16 elems per B stage (32*136) */
#define ABYTES 10240
#define BBYTES 8704
#define GSMEM (4*(ABYTES + BBYTES) + 512)

template<bool GATHER, bool AROW_PAIR, bool RELU, bool RESID, bool OUTBF16, bool QKV3>
__global__ __launch_bounds__(256, 2) void bgemm_k(
    int M, int N, int K,
    const bf16* __restrict__ A, int lda,
    const bf16* __restrict__ Bm,
    const float* __restrict__ bias,
    const float* __restrict__ resid,
    float* __restrict__ C, int ldc,
    const int* __restrict__ rowlist,
    const int* __restrict__ cnt,
    const bf16* Bm2, const float* bias2, float* C2,
    const bf16* Bm3, const float* bias3, float* C3)
{
    extern __shared__ __align__(16) char smem_raw[];
    bf16* AsBase = (bf16*)smem_raw;                 // 4 * ASTG
    bf16* BsBase = (bf16*)smem_raw + 4*ASTG;        // 4 * BSTG
    int*  rowsS  = (int*)(smem_raw + 4*(ABYTES + BBYTES));

    if (QKV3) {
        int z = blockIdx.z;
        if (z == 1) { Bm = Bm2; bias = bias2; C = C2; }
        else if (z == 2) { Bm = Bm3; bias = bias3; C = C3; }
    }
    if (GATHER) {
        int e = blockIdx.z;
        Bm      += (size_t)e * K * N;
        bias    += (size_t)e * N;
        rowlist += (size_t)e * CAP;
        cnt     += e;
    }
    int m0 = blockIdx.y * 128, n0 = blockIdx.x * 128;
    int tid = threadIdx.x, lane = tid & 31, wid = tid >> 5;
    int warpM = wid & 3, warpN = wid >> 2;

    if (GATHER) {
        int Meff = *cnt;
        if (m0 >= Meff) return;
        if (tid < 128) {
            int gidx = m0 + tid;
            rowsS[tid] = (gidx < Meff) ? rowlist[gidx] : -1;
        }
        __syncthreads();
    }

    // ---- A staging: thread -> row lm, chunks acb, acb+1 (16B = 8 bf16 each) ----
    int lm  = tid >> 1;
    int acb = (tid & 1) << 1;
    const bf16* Aptr;
    int asz = 16;
    if (GATHER) {
        int pr = rowsS[lm];
        if (pr < 0) { Aptr = A; asz = 0; }
        else Aptr = A + (size_t)(AROW_PAIR ? pr : (pr >> 1)) * lda + acb*8;
    } else {
        Aptr = A + (size_t)(m0 + lm) * lda + acb*8;
    }
    unsigned aD0 = smem_u32(&AsBase[lm*40]) + acb*16;

    // ---- B staging: thread -> row lbr (k), chunks bcb, bcb+1 ----
    int lbr = tid >> 3;
    int bcb = (tid & 7) << 1;
    const bf16* Bptr = Bm + (size_t)lbr * N + n0 + bcb*8;
    unsigned bD0 = smem_u32(&BsBase[lbr*136]) + bcb*16;

    // ---- ldmatrix base addresses (buffer 0) ----
    int lane8 = lane & 7, laneH = lane & 8, laneK = (lane & 16) >> 1;
    unsigned aAddr[2], bAddr[4];
    #pragma unroll
    for (int mt = 0; mt < 2; mt++) {
        int r = warpM*32 + mt*16 + lane8 + laneH;
        aAddr[mt] = smem_u32(&AsBase[r*40 + laneK]);
    }
    #pragma unroll
    for (int ntp = 0; ntp < 4; ntp++) {
        int kr = lane8 + laneH;
        int nc = warpN*64 + ntp*16 + laneK;
        bAddr[ntp] = smem_u32(&BsBase[kr*136 + nc]);
    }

    float acc[2][8][4];
    #pragma unroll
    for (int i = 0; i < 2; i++)
        #pragma unroll
        for (int j = 0; j < 8; j++)
            #pragma unroll
            for (int q = 0; q < 4; q++) acc[i][j][q] = 0.f;

    auto issueStage = [&](int k0, int buf) {
        unsigned ad = aD0 + buf*ABYTES;
        cp_async16(ad,      Aptr + k0,     asz);
        cp_async16(ad + 16, Aptr + k0 + 8, asz);
        const bf16* bs = Bptr + (size_t)k0 * N;
        unsigned bd = bD0 + buf*BBYTES;
        cp_async16(bd,      bs,     16);
        cp_async16(bd + 16, bs + 8, 16);
        cp_commit();
    };

    int nStages = K >> 5;
    // prologue: prefetch up to 3 stages (all K >= 768 here, so always 3)
    issueStage(0, 0);
    issueStage(32, 1);
    issueStage(64, 2);

    for (int s = 0; s < nStages; s++) {
        int rem = nStages - 1 - s;
        if (rem >= 2) cp_wait<2>();
        else if (rem == 1) cp_wait<1>();
        else cp_wait<0>();
        __syncthreads();
        if (s + 3 < nStages) issueStage((s + 3) << 5, (s + 3) & 3);

        int buf = s & 3;
        unsigned aOff = buf*ABYTES, bOff = buf*BBYTES;
        #pragma unroll
        for (int kk = 0; kk < 32; kk += 16) {
            unsigned af[2][4];
            ldsm_x4(af[0], aAddr[0] + aOff + kk*2);
            ldsm_x4(af[1], aAddr[1] + aOff + kk*2);
            #pragma unroll
            for (int ntp = 0; ntp < 4; ntp++) {
                unsigned bfr[4];
                ldsm_x4_t(bfr, bAddr[ntp] + bOff + kk*272);
                #pragma unroll
                for (int mt = 0; mt < 2; mt++) {
                    mma_bf16(acc[mt][ntp*2+0], af[mt], bfr[0], bfr[1]);
                    mma_bf16(acc[mt][ntp*2+1], af[mt], bfr[2], bfr[3]);
                }
            }
        }
    }

    // epilogue
    #pragma unroll
    for (int mt = 0; mt < 2; mt++) {
        int rr0 = warpM*32 + mt*16 + (lane >> 2);
        #pragma unroll
        for (int half = 0; half < 2; half++) {
            int rloc = rr0 + half*8;
            int crow;
            if (GATHER) {
                int pr = rowsS[rloc];
                if (pr < 0) continue;
                crow = pr;
            } else {
                crow = m0 + rloc;
            }
            #pragma unroll
            for (int nt = 0; nt < 8; nt++) {
                int col = n0 + warpN*64 + nt*8 + (lane & 3)*2;
                float v0 = acc[mt][nt][half*2 + 0] + bias[col];
                float v1 = acc[mt][nt][half*2 + 1] + bias[col + 1];
                if (RELU) { v0 = fmaxf(v0, 0.f); v1 = fmaxf(v1, 0.f); }
                if (RESID) {
                    const float* rp = resid + (size_t)crow*ldc + col;
                    v0 += rp[0]; v1 += rp[1];
                }
                if (OUTBF16) {
                    *(bf162*)((bf16*)C + (size_t)crow*ldc + col) =
                        __floats2bfloat162_rn(v0, v1);
                } else {
                    *(float2*)(C + (size_t)crow*ldc + col) = make_float2(v0, v1);
                }
            }
        }
    }
}

// ---------------- flash attention (causal), one q-row per thread ----------------
__global__ void __launch_bounds__(128, 1) attn_kernel(
    const float* __restrict__ q, const float* __restrict__ k,
    const float* __restrict__ v, bf16* __restrict__ ctx)
{
    int qt = blockIdx.x, h = blockIdx.y, b = blockIdx.z;
    int tid = threadIdx.x;
    int qidx = qt * 128 + tid;

    __shared__ float4 ksh[32*16];
    __shared__ float4 vsh[32*16];

    float4 qr[16], acc[16];
    const float4* qp = (const float4*)(q + (size_t)(b*SS + qidx)*DDIM + h*DH);
    #pragma unroll
    for (int j = 0; j < 16; j++) {
        float4 t = qp[j];
        qr[j] = make_float4(t.x*0.125f, t.y*0.125f, t.z*0.125f, t.w*0.125f);
        acc[j] = make_float4(0,0,0,0);
    }
    float m = -3.0e38f, l = 0.f;

    int kend = qt*128 + 128;
    if (kend > SS) kend = SS;
    for (int kt = 0; kt < kend; kt += 32) {
        __syncthreads();
        for (int i = tid; i < 512; i += 128) {
            int r = i >> 4, c = i & 15;
            size_t base = (size_t)(b*SS + kt + r)*DDIM + h*DH;
            ksh[i] = *((const float4*)(k + base) + c);
            vsh[i] = *((const float4*)(v + base) + c);
        }
        __syncthreads();

        float s[32];
        float tm = -3.0e38f;
        #pragma unroll
        for (int kk = 0; kk < 32; kk++) {
            const float4* kr = &ksh[kk*16];
            float d = 0.f;
            #pragma unroll
            for (int j = 0; j < 16; j++) {
                float4 kv = kr[j];
                d += qr[j].x*kv.x + qr[j].y*kv.y + qr[j].z*kv.z + qr[j].w*kv.w;
            }
            s[kk] = (kt + kk <= qidx) ? d : -1e9f;
            tm = fmaxf(tm, s[kk]);
        }
        float nm = fmaxf(m, tm);
        float c = __expf(m - nm);
        l *= c;
        #pragma unroll
        for (int j = 0; j < 16; j++) {
            acc[j].x *= c; acc[j].y *= c; acc[j].z *= c; acc[j].w *= c;
        }
        #pragma unroll
        for (int kk = 0; kk < 32; kk++) {
            float p = __expf(s[kk] - nm);
            l += p;
            const float4* vr = &vsh[kk*16];
            #pragma unroll
            for (int j = 0; j < 16; j++) {
                float4 vv = vr[j];
                acc[j].x += p*vv.x; acc[j].y += p*vv.y;
                acc[j].z += p*vv.z; acc[j].w += p*vv.w;
            }
        }
        m = nm;
    }
    float inv = 1.f / l;
    bf162* op = (bf162*)(ctx + (size_t)(b*SS + qidx)*DDIM + h*DH);
    #pragma unroll
    for (int j = 0; j < 16; j++) {
        op[2*j]   = __floats2bfloat162_rn(acc[j].x*inv, acc[j].y*inv);
        op[2*j+1] = __floats2bfloat162_rn(acc[j].z*inv, acc[j].w*inv);
    }
}

// ---------------- gate ----------------
__global__ void zero_cnt_kernel(int* cnt) {
    if (threadIdx.x < EE) cnt[threadIdx.x] = 0;
}

__global__ void gate_kernel(const float* __restrict__ h, const float* __restrict__ gw,
                            const float* __restrict__ gb, float* __restrict__ sc,
                            int* __restrict__ cnt, int* __restrict__ list)
{
    int warp = (blockIdx.x * blockDim.x + threadIdx.x) >> 5;
    if (warp >= NTOK) return;
    int lane = threadIdx.x & 31;
    float a[8] = {0,0,0,0,0,0,0,0};
    const float* hr = h + (size_t)warp * DDIM;
    for (int d = lane; d < DDIM; d += 32) {
        float hv = hr[d];
        float4 w0 = *(const float4*)(gw + (size_t)d*EE);
        float4 w1 = *(const float4*)(gw + (size_t)d*EE + 4);
        a[0]+=hv*w0.x; a[1]+=hv*w0.y; a[2]+=hv*w0.z; a[3]+=hv*w0.w;
        a[4]+=hv*w1.x; a[5]+=hv*w1.y; a[6]+=hv*w1.z; a[7]+=hv*w1.w;
    }
    #pragma unroll
    for (int e = 0; e < 8; e++)
        #pragma unroll
        for (int o = 16; o > 0; o >>= 1)
            a[e] += __shfl_down_sync(0xffffffffu, a[e], o);
    if (lane == 0) {
        float lg[8];
        #pragma unroll
        for (int e = 0; e < 8; e++) lg[e] = a[e] + gb[e];
        int i0 = 0; float v0 = lg[0];
        #pragma unroll
        for (int e = 1; e < 8; e++) if (lg[e] > v0) { v0 = lg[e]; i0 = e; }
        int i1 = -1; float v1 = -3.0e38f;
        #pragma unroll
        for (int e = 0; e < 8; e++) if (e != i0 && lg[e] > v1) { v1 = lg[e]; i1 = e; }
        float e1 = __expf(v1 - v0);
        float s0 = 1.f / (1.f + e1);
        float s1 = e1 * s0;
        sc[2*warp]   = s0;
        sc[2*warp+1] = s1;
        int p0 = atomicAdd(&cnt[i0], 1);
        list[(size_t)i0*CAP + p0] = 2*warp;
        int p1 = atomicAdd(&cnt[i1], 1);
        list[(size_t)i1*CAP + p1] = 2*warp + 1;
    }
}

// ---------------- combine ----------------
__global__ void combine_kernel(const float* __restrict__ h, const float* __restrict__ o2,
                               const float* __restrict__ sc, const float* __restrict__ xa,
                               const float* __restrict__ g, const float* __restrict__ b,
                               float* __restrict__ out)
{
    int t = blockIdx.x;
    const float* hr = h + (size_t)t*DDIM;
    const float* r0 = o2 + (size_t)(2*t)*DDIM;
    const float* r1 = o2 + (size_t)(2*t+1)*DDIM;
    float s0 = sc[2*t], s1 = sc[2*t+1];
    float tv[3];
    float s = 0.f;
    #pragma unroll
    for (int i = 0; i < 3; i++) {
        int d = threadIdx.x + i*256;
        tv[i] = hr[d] + s0*r0[d] + s1*r1[d];
        s += tv[i];
    }
    s = blockReduceSum(s);
    float mean = s * (1.f / DDIM);
    float vs = 0.f;
    #pragma unroll
    for (int i = 0; i < 3; i++) { float d = tv[i] - mean; vs += d*d; }
    vs = blockReduceSum(vs);
    float rstd = rsqrtf(vs * (1.f / DDIM) + 1e-5f);
    #pragma unroll
    for (int i = 0; i < 3; i++) {
        int d = threadIdx.x + i*256;
        out[(size_t)t*DDIM + d] = xa[(size_t)t*DDIM + d] + (tv[i] - mean)*rstd*g[d] + b[d];
    }
}

// ---------------- launch ----------------
extern "C" void kernel_launch(void* const* d_in, const int* in_sizes, int n_in,
                              void* d_out, int out_size)
{
    const float* x        = (const float*)d_in[0];
    const float* ln_a_g   = (const float*)d_in[2];
    const float* ln_a_b   = (const float*)d_in[3];
    const float* wq       = (const float*)d_in[4];
    const float* bq       = (const float*)d_in[5];
    const float* wk       = (const float*)d_in[6];
    const float* bk       = (const float*)d_in[7];
    const float* wv       = (const float*)d_in[8];
    const float* bv       = (const float*)d_in[9];
    const float* wo       = (const float*)d_in[10];
    const float* bo       = (const float*)d_in[11];
    const float* ln_f_g   = (const float*)d_in[12];
    const float* ln_f_b   = (const float*)d_in[13];
    const float* gate_w   = (const float*)d_in[14];
    const float* gate_b   = (const float*)d_in[15];
    const float* w1       = (const float*)d_in[16];
    const float* b1       = (const float*)d_in[17];
    const float* w2       = (const float*)d_in[18];
    const float* b2       = (const float*)d_in[19];
    const float* moe_g    = (const float*)d_in[20];
    const float* moe_b    = (const float*)d_in[21];
    float* out = (float*)d_out;

    bf16 *a, *ctx, *hrb, *y1, *bwq, *bwk, *bwv, *bwo, *bw1, *bw2;
    float *qb, *kb, *vb, *xa, *h, *o2, *sc;
    int *cnt, *list;
    cudaGetSymbolAddress((void**)&a,   g_a);
    cudaGetSymbolAddress((void**)&qb,  g_q);
    cudaGetSymbolAddress((void**)&kb,  g_k);
    cudaGetSymbolAddress((void**)&vb,  g_v);
    cudaGetSymbolAddress((void**)&ctx, g_ctx);
    cudaGetSymbolAddress((void**)&xa,  g_xa);
    cudaGetSymbolAddress((void**)&h,   g_h);
    cudaGetSymbolAddress((void**)&hrb, g_hr);
    cudaGetSymbolAddress((void**)&y1,  g_y1);
    cudaGetSymbolAddress((void**)&o2,  g_o2);
    cudaGetSymbolAddress((void**)&sc,  g_sc);
    cudaGetSymbolAddress((void**)&cnt, g_cnt);
    cudaGetSymbolAddress((void**)&list,g_list);
    cudaGetSymbolAddress((void**)&bwq, g_bwq);
    cudaGetSymbolAddress((void**)&bwk, g_bwk);
    cudaGetSymbolAddress((void**)&bwv, g_bwv);
    cudaGetSymbolAddress((void**)&bwo, g_bwo);
    cudaGetSymbolAddress((void**)&bw1, g_bw1);
    cudaGetSymbolAddress((void**)&bw2, g_bw2);

    // opt-in to >48KB dynamic smem (host-side attribute, set every call; idempotent)
    cudaFuncSetAttribute(bgemm_k<false,false,false,false,false,true>,
                         cudaFuncAttributeMaxDynamicSharedMemorySize, GSMEM);
    cudaFuncSetAttribute(bgemm_k<false,false,false,true,false,false>,
                         cudaFuncAttributeMaxDynamicSharedMemorySize, GSMEM);
    cudaFuncSetAttribute(bgemm_k<true,false,true,false,true,false>,
                         cudaFuncAttributeMaxDynamicSharedMemorySize, GSMEM);
    cudaFuncSetAttribute(bgemm_k<true,true,false,false,false,false>,
                         cudaFuncAttributeMaxDynamicSharedMemorySize, GSMEM);

    // 0) weight conversions f32 -> bf16
    {
        int nqkv4 = DDIM*DDIM/4;
        int gq = (nqkv4 + 255)/256;
        conv_bf16_kernel<<<gq, 256>>>(wq, bwq, nqkv4);
        conv_bf16_kernel<<<gq, 256>>>(wk, bwk, nqkv4);
        conv_bf16_kernel<<<gq, 256>>>(wv, bwv, nqkv4);
        conv_bf16_kernel<<<gq, 256>>>(wo, bwo, nqkv4);
        int nff4 = EE*DDIM*HID/4;
        int gf = (nff4 + 255)/256;
        conv_bf16_kernel<<<gf, 256>>>(w1, bw1, nff4);
        conv_bf16_kernel<<<gf, 256>>>(w2, bw2, nff4);
    }

    // 1) a = bf16(ln_attn(x))
    ln_kernel<1><<<NTOK, 256>>>(x, ln_a_g, ln_a_b, nullptr, a);

    // 2) fused q,k,v projections (grid.z selects weight/out)
    dim3 gQKV(DDIM/128, NTOK/128, 3);
    bgemm_k<false,false,false,false,false,true><<<gQKV, 256, GSMEM>>>(
        NTOK, DDIM, DDIM, a, DDIM, bwq, bq, nullptr, qb, DDIM, nullptr, nullptr,
        bwk, bk, kb, bwv, bv, vb);

    // 3) flash attention (causal), ctx bf16
    attn_kernel<<<dim3(SS/128, HH, BB), 128>>>(qb, kb, vb, ctx);

    // 4) xa = x + ctx @ wo + bo
    dim3 gO(DDIM/128, NTOK/128, 1);
    bgemm_k<false,false,false,true,false,false><<<gO, 256, GSMEM>>>(
        NTOK, DDIM, DDIM, ctx, DDIM, bwo, bo, x, xa, DDIM, nullptr, nullptr,
        nullptr, nullptr, nullptr, nullptr, nullptr, nullptr);

    // 5) h = ln_ff(xa) (f32) + hr (bf16)
    ln_kernel<2><<<NTOK, 256>>>(xa, ln_f_g, ln_f_b, h, hrb);

    // 6) gate: top-2 per token + per-expert pair lists
    zero_cnt_kernel<<<1, 32>>>(cnt);
    gate_kernel<<<NTOK/8, 256>>>(h, gate_w, gate_b, sc, cnt, list);

    // 7) expert GEMM1: y1[pair] = bf16(relu(hr[token] @ w1[e] + b1[e]))
    bgemm_k<true,false,true,false,true,false><<<dim3(HID/128, CAP/128, EE), 256, GSMEM>>>(
        CAP, HID, DDIM, hrb, DDIM, bw1, b1, nullptr, (float*)y1, HID, list, cnt,
        nullptr, nullptr, nullptr, nullptr, nullptr, nullptr);

    // 8) expert GEMM2: o2[pair] = y1[pair] @ w2[e] + b2[e]
    bgemm_k<true,true,false,false,false,false><<<dim3(DDIM/128, CAP/128, EE), 256, GSMEM>>>(
        CAP, DDIM, HID, y1, HID, bw2, b2, nullptr, o2, DDIM, list, cnt,
        nullptr, nullptr, nullptr, nullptr, nullptr, nullptr);

    // 9) combine + post-LN + final residual
    combine_kernel<<<NTOK, 256>>>(h, o2, sc, xa, moe_g, moe_b, out);
}

// round 11
// speedup vs baseline: 2.6989x; 1.7116x over previous
#include <cuda_runtime.h>
#include <cuda_bf16.h>

#define BB 4
#define SS 1024
#define DDIM 768
#define HH 12
#define EE 8
#define HID 3072
#define DH 64
#define NTOK (BB*SS)
#define CAP (NTOK*2)

typedef __nv_bfloat16 bf16;
typedef __nv_bfloat162 bf162;

// ---------------- scratch (device globals: no allocation allowed) ----------------
__device__ bf16  g_a[NTOK*DDIM];     // ln_attn(x), bf16
__device__ bf16  g_q[NTOK*DDIM];
__device__ bf16  g_k[NTOK*DDIM];
__device__ bf16  g_v[NTOK*DDIM];
__device__ bf16  g_ctx[NTOK*DDIM];   // attention out, bf16
__device__ float g_xa[NTOK*DDIM];    // x + attn_out
__device__ float g_h[NTOK*DDIM];     // ln_ff(xa) full precision
__device__ bf16  g_hr[NTOK*DDIM];    // ln_ff(xa) bf16
__device__ bf16  g_y1[CAP*HID];      // expert hidden, bf16
__device__ float g_o2[CAP*DDIM];     // expert out
__device__ float g_sc[CAP];
__device__ int   g_cnt[EE];
__device__ int   g_list[EE*CAP];
// bf16 weight copies
__device__ bf16  g_bwq[DDIM*DDIM];
__device__ bf16  g_bwk[DDIM*DDIM];
__device__ bf16  g_bwv[DDIM*DDIM];
__device__ bf16  g_bwo[DDIM*DDIM];
__device__ bf16  g_bw1[EE*DDIM*HID];
__device__ bf16  g_bw2[EE*HID*DDIM];

// ---------------- helpers ----------------
__device__ __forceinline__ unsigned smem_u32(const void* p) {
    return (unsigned)__cvta_generic_to_shared(p);
}
__device__ __forceinline__ void cp_async16(unsigned dst, const void* src, int srcsize) {
    asm volatile("cp.async.cg.shared.global [%0], [%1], 16, %2;"
                 :: "r"(dst), "l"(src), "r"(srcsize));
}
__device__ __forceinline__ void cp_commit() { asm volatile("cp.async.commit_group;"); }
template<int N>
__device__ __forceinline__ void cp_wait() { asm volatile("cp.async.wait_group %0;" :: "n"(N)); }

__device__ __forceinline__ void ldsm_x4(unsigned* r, unsigned addr) {
    asm volatile("ldmatrix.sync.aligned.m8n8.x4.shared.b16 {%0,%1,%2,%3}, [%4];"
        : "=r"(r[0]), "=r"(r[1]), "=r"(r[2]), "=r"(r[3]) : "r"(addr));
}
__device__ __forceinline__ void ldsm_x4_t(unsigned* r, unsigned addr) {
    asm volatile("ldmatrix.sync.aligned.m8n8.x4.trans.shared.b16 {%0,%1,%2,%3}, [%4];"
        : "=r"(r[0]), "=r"(r[1]), "=r"(r[2]), "=r"(r[3]) : "r"(addr));
}
__device__ __forceinline__ void mma_bf16(float c[4], const unsigned a[4],
                                         unsigned b0, unsigned b1) {
    asm volatile("mma.sync.aligned.m16n8k16.row.col.f32.bf16.bf16.f32 "
        "{%0,%1,%2,%3}, {%4,%5,%6,%7}, {%8,%9}, {%0,%1,%2,%3};"
        : "+f"(c[0]), "+f"(c[1]), "+f"(c[2]), "+f"(c[3])
        : "r"(a[0]), "r"(a[1]), "r"(a[2]), "r"(a[3]), "r"(b0), "r"(b1));
}
__device__ __forceinline__ unsigned pack_bf16(float a, float b) {
    bf162 t = __floats2bfloat162_rn(a, b);
    return *(unsigned*)&t;
}

__device__ __forceinline__ float blockReduceSum(float v) {
    __shared__ float sh[33];
    __syncthreads();
    int lane = threadIdx.x & 31, wid = threadIdx.x >> 5;
    #pragma unroll
    for (int o = 16; o > 0; o >>= 1) v += __shfl_down_sync(0xffffffffu, v, o);
    if (lane == 0) sh[wid] = v;
    __syncthreads();
    float r = (threadIdx.x < (blockDim.x >> 5)) ? sh[threadIdx.x] : 0.f;
    if (wid == 0) {
        #pragma unroll
        for (int o = 16; o > 0; o >>= 1) r += __shfl_down_sync(0xffffffffu, r, o);
        if (lane == 0) sh[32] = r;
    }
    __syncthreads();
    return sh[32];
}

// ---------------- weight conversion f32 -> bf16 ----------------
__global__ void conv_bf16_kernel(const float* __restrict__ src, bf16* __restrict__ dst, int n4) {
    int i = blockIdx.x * blockDim.x + threadIdx.x;
    if (i < n4) {
        float4 v = *(const float4*)(src + (size_t)i*4);
        bf162* d = (bf162*)(dst + (size_t)i*4);
        d[0] = __floats2bfloat162_rn(v.x, v.y);
        d[1] = __floats2bfloat162_rn(v.z, v.w);
    }
}

// ---------------- layernorm ----------------
template<int MODE>
__global__ void ln_kernel(const float* __restrict__ x, const float* __restrict__ g,
                          const float* __restrict__ b, float* __restrict__ out,
                          bf16* __restrict__ out_b) {
    int row = blockIdx.x;
    const float* xr = x + (size_t)row * DDIM;
    float v[3];
    float s = 0.f;
    #pragma unroll
    for (int i = 0; i < 3; i++) { v[i] = xr[threadIdx.x + i*256]; s += v[i]; }
    s = blockReduceSum(s);
    float mean = s * (1.f / DDIM);
    float vs = 0.f;
    #pragma unroll
    for (int i = 0; i < 3; i++) { float d = v[i] - mean; vs += d*d; }
    vs = blockReduceSum(vs);
    float rstd = rsqrtf(vs * (1.f / DDIM) + 1e-5f);
    #pragma unroll
    for (int i = 0; i < 3; i++) {
        int d = threadIdx.x + i*256;
        float y = (v[i] - mean) * rstd * g[d] + b[d];
        if (MODE == 1) out_b[(size_t)row*DDIM + d] = __float2bfloat16_rn(y);
        if (MODE == 2) {
            out  [(size_t)row*DDIM + d] = y;
            out_b[(size_t)row*DDIM + d] = __float2bfloat16_rn(y);
        }
    }
}

// ---------------- bf16 tensor-core GEMM, 4-stage cp.async pipeline ----------------
#define ASTG 5120
#define BSTG 4352
#define ABYTES 10240
#define BBYTES 8704
#define GSMEM (4*(ABYTES + BBYTES) + 512)

template<bool GATHER, bool AROW_PAIR, bool RELU, bool RESID, bool OUTBF16, bool QKV3>
__global__ __launch_bounds__(256, 2) void bgemm_k(
    int M, int N, int K,
    const bf16* __restrict__ A, int lda,
    const bf16* __restrict__ Bm,
    const float* __restrict__ bias,
    const float* __restrict__ resid,
    float* __restrict__ C, int ldc,
    const int* __restrict__ rowlist,
    const int* __restrict__ cnt,
    const bf16* Bm2, const float* bias2, float* C2,
    const bf16* Bm3, const float* bias3, float* C3)
{
    extern __shared__ __align__(16) char smem_raw[];
    bf16* AsBase = (bf16*)smem_raw;
    bf16* BsBase = (bf16*)smem_raw + 4*ASTG;
    int*  rowsS  = (int*)(smem_raw + 4*(ABYTES + BBYTES));

    if (QKV3) {
        int z = blockIdx.z;
        if (z == 1) { Bm = Bm2; bias = bias2; C = C2; }
        else if (z == 2) { Bm = Bm3; bias = bias3; C = C3; }
    }
    if (GATHER) {
        int e = blockIdx.z;
        Bm      += (size_t)e * K * N;
        bias    += (size_t)e * N;
        rowlist += (size_t)e * CAP;
        cnt     += e;
    }
    int m0 = blockIdx.y * 128, n0 = blockIdx.x * 128;
    int tid = threadIdx.x, lane = tid & 31, wid = tid >> 5;
    int warpM = wid & 3, warpN = wid >> 2;

    if (GATHER) {
        int Meff = *cnt;
        if (m0 >= Meff) return;
        if (tid < 128) {
            int gidx = m0 + tid;
            rowsS[tid] = (gidx < Meff) ? rowlist[gidx] : -1;
        }
        __syncthreads();
    }

    int lm  = tid >> 1;
    int acb = (tid & 1) << 1;
    const bf16* Aptr;
    int asz = 16;
    if (GATHER) {
        int pr = rowsS[lm];
        if (pr < 0) { Aptr = A; asz = 0; }
        else Aptr = A + (size_t)(AROW_PAIR ? pr : (pr >> 1)) * lda + acb*8;
    } else {
        Aptr = A + (size_t)(m0 + lm) * lda + acb*8;
    }
    unsigned aD0 = smem_u32(&AsBase[lm*40]) + acb*16;

    int lbr = tid >> 3;
    int bcb = (tid & 7) << 1;
    const bf16* Bptr = Bm + (size_t)lbr * N + n0 + bcb*8;
    unsigned bD0 = smem_u32(&BsBase[lbr*136]) + bcb*16;

    int lane8 = lane & 7, laneH = lane & 8, laneK = (lane & 16) >> 1;
    unsigned aAddr[2], bAddr[4];
    #pragma unroll
    for (int mt = 0; mt < 2; mt++) {
        int r = warpM*32 + mt*16 + lane8 + laneH;
        aAddr[mt] = smem_u32(&AsBase[r*40 + laneK]);
    }
    #pragma unroll
    for (int ntp = 0; ntp < 4; ntp++) {
        int kr = lane8 + laneH;
        int nc = warpN*64 + ntp*16 + laneK;
        bAddr[ntp] = smem_u32(&BsBase[kr*136 + nc]);
    }

    float acc[2][8][4];
    #pragma unroll
    for (int i = 0; i < 2; i++)
        #pragma unroll
        for (int j = 0; j < 8; j++)
            #pragma unroll
            for (int q = 0; q < 4; q++) acc[i][j][q] = 0.f;

    auto issueStage = [&](int k0, int buf) {
        unsigned ad = aD0 + buf*ABYTES;
        cp_async16(ad,      Aptr + k0,     asz);
        cp_async16(ad + 16, Aptr + k0 + 8, asz);
        const bf16* bs = Bptr + (size_t)k0 * N;
        unsigned bd = bD0 + buf*BBYTES;
        cp_async16(bd,      bs,     16);
        cp_async16(bd + 16, bs + 8, 16);
        cp_commit();
    };

    int nStages = K >> 5;
    issueStage(0, 0);
    issueStage(32, 1);
    issueStage(64, 2);

    for (int s = 0; s < nStages; s++) {
        int rem = nStages - 1 - s;
        if (rem >= 2) cp_wait<2>();
        else if (rem == 1) cp_wait<1>();
        else cp_wait<0>();
        __syncthreads();
        if (s + 3 < nStages) issueStage((s + 3) << 5, (s + 3) & 3);

        int buf = s & 3;
        unsigned aOff = buf*ABYTES, bOff = buf*BBYTES;
        #pragma unroll
        for (int kk = 0; kk < 32; kk += 16) {
            unsigned af[2][4];
            ldsm_x4(af[0], aAddr[0] + aOff + kk*2);
            ldsm_x4(af[1], aAddr[1] + aOff + kk*2);
            #pragma unroll
            for (int ntp = 0; ntp < 4; ntp++) {
                unsigned bfr[4];
                ldsm_x4_t(bfr, bAddr[ntp] + bOff + kk*272);
                #pragma unroll
                for (int mt = 0; mt < 2; mt++) {
                    mma_bf16(acc[mt][ntp*2+0], af[mt], bfr[0], bfr[1]);
                    mma_bf16(acc[mt][ntp*2+1], af[mt], bfr[2], bfr[3]);
                }
            }
        }
    }

    #pragma unroll
    for (int mt = 0; mt < 2; mt++) {
        int rr0 = warpM*32 + mt*16 + (lane >> 2);
        #pragma unroll
        for (int half = 0; half < 2; half++) {
            int rloc = rr0 + half*8;
            int crow;
            if (GATHER) {
                int pr = rowsS[rloc];
                if (pr < 0) continue;
                crow = pr;
            } else {
                crow = m0 + rloc;
            }
            #pragma unroll
            for (int nt = 0; nt < 8; nt++) {
                int col = n0 + warpN*64 + nt*8 + (lane & 3)*2;
                float v0 = acc[mt][nt][half*2 + 0] + bias[col];
                float v1 = acc[mt][nt][half*2 + 1] + bias[col + 1];
                if (RELU) { v0 = fmaxf(v0, 0.f); v1 = fmaxf(v1, 0.f); }
                if (RESID) {
                    const float* rp = resid + (size_t)crow*ldc + col;
                    v0 += rp[0]; v1 += rp[1];
                }
                if (OUTBF16) {
                    *(bf162*)((bf16*)C + (size_t)crow*ldc + col) =
                        __floats2bfloat162_rn(v0, v1);
                } else {
                    *(float2*)(C + (size_t)crow*ldc + col) = make_float2(v0, v1);
                }
            }
        }
    }
}

// ---------------- tensor-core flash attention (causal, bf16 mma) ----------------
// 64 q-rows per CTA, 4 warps (each m16). K/V tiles of 64 keys, double-buffered.
// smem rows stride 72 bf16 (144B) -> conflict-free ldmatrix (trans & non-trans).
#define ATS 72

__global__ void __launch_bounds__(128) attn_tc_kernel(
    const bf16* __restrict__ q, const bf16* __restrict__ k,
    const bf16* __restrict__ v, bf16* __restrict__ ctx)
{
    __shared__ __align__(16) bf16 Qs[64*ATS];
    __shared__ __align__(16) bf16 Ks[2][64*ATS];
    __shared__ __align__(16) bf16 Vs[2][64*ATS];

    int qt = blockIdx.x, h = blockIdx.y, b = blockIdx.z;
    int q0 = qt * 64;
    int tid = threadIdx.x, lane = tid & 31, w = tid >> 5;

    // staging: thread -> row tid>>1, 4 chunks of 16B at (tid&1)*4
    int srow = tid >> 1;
    int sc0  = (tid & 1) * 4;
    const bf16* qg = q + (size_t)(b*SS + q0 + srow)*DDIM + h*DH + sc0*8;
    unsigned qDst = smem_u32(&Qs[srow*ATS]) + sc0*16;
    unsigned kDst = smem_u32(&Ks[0][srow*ATS]) + sc0*16;
    unsigned vDst = smem_u32(&Vs[0][srow*ATS]) + sc0*16;
    const bf16* kg0 = k + (size_t)(b*SS + srow)*DDIM + h*DH + sc0*8;
    const bf16* vg0 = v + (size_t)(b*SS + srow)*DDIM + h*DH + sc0*8;

    auto issueKV = [&](int kt, int buf) {
        unsigned kd = kDst + buf*(64*ATS*2);
        unsigned vd = vDst + buf*(64*ATS*2);
        const bf16* kgp = kg0 + (size_t)kt*DDIM;
        const bf16* vgp = vg0 + (size_t)kt*DDIM;
        #pragma unroll
        for (int j = 0; j < 4; j++) {
            cp_async16(kd + j*16, kgp + j*8, 16);
            cp_async16(vd + j*16, vgp + j*8, 16);
        }
        cp_commit();
    };

    // prologue: Q + tile 0 in one group
    #pragma unroll
    for (int j = 0; j < 4; j++) cp_async16(qDst + j*16, qg + j*8, 16);
    issueKV(0, 0);

    // ldmatrix lane addressing pieces
    int l15 = lane & 15;
    int lH8 = (lane >> 4) << 3;           // 0 or 8
    int lB8 = ((lane >> 3) & 1) << 3;     // 0 or 8
    int bRowP = lH8 + (lane & 7);         // for score-B (K): key offset pattern

    unsigned qf[4][4];
    float m0 = -1e30f, m1 = -1e30f, l0 = 0.f, l1 = 0.f;
    float oa[8][4];
    #pragma unroll
    for (int j = 0; j < 8; j++)
        #pragma unroll
        for (int e = 0; e < 4; e++) oa[j][e] = 0.f;

    int r0loc = lane >> 2;                // fragment row within m16
    int rowg0 = q0 + 16*w + r0loc;        // global q row (this thread, low)
    int rowg1 = rowg0 + 8;
    int c2 = (lane & 3) * 2;

    int nt = q0/64 + 1;
    for (int t = 0; t < nt; t++) {
        cp_wait<0>();
        __syncthreads();
        if (t == 0) {
            // load Q fragments once
            #pragma unroll
            for (int kk = 0; kk < 4; kk++)
                ldsm_x4(qf[kk], smem_u32(&Qs[(16*w + l15)*ATS + kk*16 + lH8]));
        }
        if (t + 1 < nt) issueKV((t+1)*64, (t+1) & 1);

        int buf = t & 1;
        int kt = t * 64;
        const bf16* KsB = Ks[buf];
        const bf16* VsB = Vs[buf];

        // ---- scores S = Q K^T (fp32 accum) ----
        float sf[8][4];
        #pragma unroll
        for (int j = 0; j < 8; j++)
            #pragma unroll
            for (int e = 0; e < 4; e++) sf[j][e] = 0.f;
        #pragma unroll
        for (int kk = 0; kk < 4; kk++) {
            #pragma unroll
            for (int j2 = 0; j2 < 4; j2++) {
                unsigned bk[4];
                ldsm_x4(bk, smem_u32(&KsB[(16*j2 + bRowP)*ATS + kk*16 + lB8]));
                mma_bf16(sf[2*j2+0], qf[kk], bk[0], bk[1]);
                mma_bf16(sf[2*j2+1], qf[kk], bk[2], bk[3]);
            }
        }
        // scale + causal mask (diagonal tile only)
        #pragma unroll
        for (int j = 0; j < 8; j++)
            #pragma unroll
            for (int e = 0; e < 4; e++) sf[j][e] *= 0.125f;
        if (kt == q0) {
            #pragma unroll
            for (int j = 0; j < 8; j++) {
                int col = kt + 8*j + c2;
                if (col     > rowg0) sf[j][0] = -1e30f;
                if (col + 1 > rowg0) sf[j][1] = -1e30f;
                if (col     > rowg1) sf[j][2] = -1e30f;
                if (col + 1 > rowg1) sf[j][3] = -1e30f;
            }
        }
        // ---- online softmax ----
        float tm0 = -1e30f, tm1 = -1e30f;
        #pragma unroll
        for (int j = 0; j < 8; j++) {
            tm0 = fmaxf(tm0, fmaxf(sf[j][0], sf[j][1]));
            tm1 = fmaxf(tm1, fmaxf(sf[j][2], sf[j][3]));
        }
        tm0 = fmaxf(tm0, __shfl_xor_sync(0xffffffffu, tm0, 1));
        tm0 = fmaxf(tm0, __shfl_xor_sync(0xffffffffu, tm0, 2));
        tm1 = fmaxf(tm1, __shfl_xor_sync(0xffffffffu, tm1, 1));
        tm1 = fmaxf(tm1, __shfl_xor_sync(0xffffffffu, tm1, 2));
        float nm0 = fmaxf(m0, tm0), nm1 = fmaxf(m1, tm1);
        float cc0 = __expf(m0 - nm0), cc1 = __expf(m1 - nm1);
        l0 *= cc0; l1 *= cc1;
        #pragma unroll
        for (int j = 0; j < 8; j++) {
            oa[j][0] *= cc0; oa[j][1] *= cc0;
            oa[j][2] *= cc1; oa[j][3] *= cc1;
        }
        float ps0 = 0.f, ps1 = 0.f;
        #pragma unroll
        for (int j = 0; j < 8; j++) {
            sf[j][0] = __expf(sf[j][0] - nm0);
            sf[j][1] = __expf(sf[j][1] - nm0);
            sf[j][2] = __expf(sf[j][2] - nm1);
            sf[j][3] = __expf(sf[j][3] - nm1);
            ps0 += sf[j][0] + sf[j][1];
            ps1 += sf[j][2] + sf[j][3];
        }
        l0 += ps0; l1 += ps1; m0 = nm0; m1 = nm1;

        // pack P to bf16 A-fragments (register-only)
        unsigned pf[4][4];
        #pragma unroll
        for (int t2 = 0; t2 < 4; t2++) {
            pf[t2][0] = pack_bf16(sf[2*t2][0],   sf[2*t2][1]);
            pf[t2][1] = pack_bf16(sf[2*t2][2],   sf[2*t2][3]);
            pf[t2][2] = pack_bf16(sf[2*t2+1][0], sf[2*t2+1][1]);
            pf[t2][3] = pack_bf16(sf[2*t2+1][2], sf[2*t2+1][3]);
        }
        // ---- O += P V ----
        #pragma unroll
        for (int t2 = 0; t2 < 4; t2++) {
            #pragma unroll
            for (int g = 0; g < 4; g++) {
                unsigned bv[4];
                ldsm_x4_t(bv, smem_u32(&VsB[(16*t2 + l15)*ATS + 16*g + lH8]));
                mma_bf16(oa[2*g+0], pf[t2], bv[0], bv[1]);
                mma_bf16(oa[2*g+1], pf[t2], bv[2], bv[3]);
            }
        }
        __syncthreads();   // before next iteration's issue overwrites buf^1
    }

    // final row sums across quad
    l0 += __shfl_xor_sync(0xffffffffu, l0, 1);
    l0 += __shfl_xor_sync(0xffffffffu, l0, 2);
    l1 += __shfl_xor_sync(0xffffffffu, l1, 1);
    l1 += __shfl_xor_sync(0xffffffffu, l1, 2);
    float inv0 = 1.f / l0, inv1 = 1.f / l1;

    bf16* c0p = ctx + (size_t)(b*SS + rowg0)*DDIM + h*DH + c2;
    bf16* c1p = ctx + (size_t)(b*SS + rowg1)*DDIM + h*DH + c2;
    #pragma unroll
    for (int j = 0; j < 8; j++) {
        *(bf162*)(c0p + 8*j) = __floats2bfloat162_rn(oa[j][0]*inv0, oa[j][1]*inv0);
        *(bf162*)(c1p + 8*j) = __floats2bfloat162_rn(oa[j][2]*inv1, oa[j][3]*inv1);
    }
}

// ---------------- gate ----------------
__global__ void zero_cnt_kernel(int* cnt) {
    if (threadIdx.x < EE) cnt[threadIdx.x] = 0;
}

__global__ void gate_kernel(const float* __restrict__ h, const float* __restrict__ gw,
                            const float* __restrict__ gb, float* __restrict__ sc,
                            int* __restrict__ cnt, int* __restrict__ list)
{
    int warp = (blockIdx.x * blockDim.x + threadIdx.x) >> 5;
    if (warp >= NTOK) return;
    int lane = threadIdx.x & 31;
    float a[8] = {0,0,0,0,0,0,0,0};
    const float* hr = h + (size_t)warp * DDIM;
    for (int d = lane; d < DDIM; d += 32) {
        float hv = hr[d];
        float4 w0 = *(const float4*)(gw + (size_t)d*EE);
        float4 w1 = *(const float4*)(gw + (size_t)d*EE + 4);
        a[0]+=hv*w0.x; a[1]+=hv*w0.y; a[2]+=hv*w0.z; a[3]+=hv*w0.w;
        a[4]+=hv*w1.x; a[5]+=hv*w1.y; a[6]+=hv*w1.z; a[7]+=hv*w1.w;
    }
    #pragma unroll
    for (int e = 0; e < 8; e++)
        #pragma unroll
        for (int o = 16; o > 0; o >>= 1)
            a[e] += __shfl_down_sync(0xffffffffu, a[e], o);
    if (lane == 0) {
        float lg[8];
        #pragma unroll
        for (int e = 0; e < 8; e++) lg[e] = a[e] + gb[e];
        int i0 = 0; float v0 = lg[0];
        #pragma unroll
        for (int e = 1; e < 8; e++) if (lg[e] > v0) { v0 = lg[e]; i0 = e; }
        int i1 = -1; float v1 = -3.0e38f;
        #pragma unroll
        for (int e = 0; e < 8; e++) if (e != i0 && lg[e] > v1) { v1 = lg[e]; i1 = e; }
        float e1 = __expf(v1 - v0);
        float s0 = 1.f / (1.f + e1);
        float s1 = e1 * s0;
        sc[2*warp]   = s0;
        sc[2*warp+1] = s1;
        int p0 = atomicAdd(&cnt[i0], 1);
        list[(size_t)i0*CAP + p0] = 2*warp;
        int p1 = atomicAdd(&cnt[i1], 1);
        list[(size_t)i1*CAP + p1] = 2*warp + 1;
    }
}

// ---------------- combine ----------------
__global__ void combine_kernel(const float* __restrict__ h, const float* __restrict__ o2,
                               const float* __restrict__ sc, const float* __restrict__ xa,
                               const float* __restrict__ g, const float* __restrict__ b,
                               float* __restrict__ out)
{
    int t = blockIdx.x;
    const float* hr = h + (size_t)t*DDIM;
    const float* r0 = o2 + (size_t)(2*t)*DDIM;
    const float* r1 = o2 + (size_t)(2*t+1)*DDIM;
    float s0 = sc[2*t], s1 = sc[2*t+1];
    float tv[3];
    float s = 0.f;
    #pragma unroll
    for (int i = 0; i < 3; i++) {
        int d = threadIdx.x + i*256;
        tv[i] = hr[d] + s0*r0[d] + s1*r1[d];
        s += tv[i];
    }
    s = blockReduceSum(s);
    float mean = s * (1.f / DDIM);
    float vs = 0.f;
    #pragma unroll
    for (int i = 0; i < 3; i++) { float d = tv[i] - mean; vs += d*d; }
    vs = blockReduceSum(vs);
    float rstd = rsqrtf(vs * (1.f / DDIM) + 1e-5f);
    #pragma unroll
    for (int i = 0; i < 3; i++) {
        int d = threadIdx.x + i*256;
        out[(size_t)t*DDIM + d] = xa[(size_t)t*DDIM + d] + (tv[i] - mean)*rstd*g[d] + b[d];
    }
}

// ---------------- launch ----------------
extern "C" void kernel_launch(void* const* d_in, const int* in_sizes, int n_in,
                              void* d_out, int out_size)
{
    const float* x        = (const float*)d_in[0];
    const float* ln_a_g   = (const float*)d_in[2];
    const float* ln_a_b   = (const float*)d_in[3];
    const float* wq       = (const float*)d_in[4];
    const float* bq       = (const float*)d_in[5];
    const float* wk       = (const float*)d_in[6];
    const float* bk       = (const float*)d_in[7];
    const float* wv       = (const float*)d_in[8];
    const float* bv       = (const float*)d_in[9];
    const float* wo       = (const float*)d_in[10];
    const float* bo       = (const float*)d_in[11];
    const float* ln_f_g   = (const float*)d_in[12];
    const float* ln_f_b   = (const float*)d_in[13];
    const float* gate_w   = (const float*)d_in[14];
    const float* gate_b   = (const float*)d_in[15];
    const float* w1       = (const float*)d_in[16];
    const float* b1       = (const float*)d_in[17];
    const float* w2       = (const float*)d_in[18];
    const float* b2       = (const float*)d_in[19];
    const float* moe_g    = (const float*)d_in[20];
    const float* moe_b    = (const float*)d_in[21];
    float* out = (float*)d_out;

    bf16 *a, *qb, *kb, *vb, *ctx, *hrb, *y1, *bwq, *bwk, *bwv, *bwo, *bw1, *bw2;
    float *xa, *h, *o2, *sc;
    int *cnt, *list;
    cudaGetSymbolAddress((void**)&a,   g_a);
    cudaGetSymbolAddress((void**)&qb,  g_q);
    cudaGetSymbolAddress((void**)&kb,  g_k);
    cudaGetSymbolAddress((void**)&vb,  g_v);
    cudaGetSymbolAddress((void**)&ctx, g_ctx);
    cudaGetSymbolAddress((void**)&xa,  g_xa);
    cudaGetSymbolAddress((void**)&h,   g_h);
    cudaGetSymbolAddress((void**)&hrb, g_hr);
    cudaGetSymbolAddress((void**)&y1,  g_y1);
    cudaGetSymbolAddress((void**)&o2,  g_o2);
    cudaGetSymbolAddress((void**)&sc,  g_sc);
    cudaGetSymbolAddress((void**)&cnt, g_cnt);
    cudaGetSymbolAddress((void**)&list,g_list);
    cudaGetSymbolAddress((void**)&bwq, g_bwq);
    cudaGetSymbolAddress((void**)&bwk, g_bwk);
    cudaGetSymbolAddress((void**)&bwv, g_bwv);
    cudaGetSymbolAddress((void**)&bwo, g_bwo);
    cudaGetSymbolAddress((void**)&bw1, g_bw1);
    cudaGetSymbolAddress((void**)&bw2, g_bw2);

    cudaFuncSetAttribute(bgemm_k<false,false,false,false,true,true>,
                         cudaFuncAttributeMaxDynamicSharedMemorySize, GSMEM);
    cudaFuncSetAttribute(bgemm_k<false,false,false,true,false,false>,
                         cudaFuncAttributeMaxDynamicSharedMemorySize, GSMEM);
    cudaFuncSetAttribute(bgemm_k<true,false,true,false,true,false>,
                         cudaFuncAttributeMaxDynamicSharedMemorySize, GSMEM);
    cudaFuncSetAttribute(bgemm_k<true,true,false,false,false,false>,
                         cudaFuncAttributeMaxDynamicSharedMemorySize, GSMEM);

    // 0) weight conversions f32 -> bf16
    {
        int nqkv4 = DDIM*DDIM/4;
        int gq = (nqkv4 + 255)/256;
        conv_bf16_kernel<<<gq, 256>>>(wq, bwq, nqkv4);
        conv_bf16_kernel<<<gq, 256>>>(wk, bwk, nqkv4);
        conv_bf16_kernel<<<gq, 256>>>(wv, bwv, nqkv4);
        conv_bf16_kernel<<<gq, 256>>>(wo, bwo, nqkv4);
        int nff4 = EE*DDIM*HID/4;
        int gf = (nff4 + 255)/256;
        conv_bf16_kernel<<<gf, 256>>>(w1, bw1, nff4);
        conv_bf16_kernel<<<gf, 256>>>(w2, bw2, nff4);
    }

    // 1) a = bf16(ln_attn(x))
    ln_kernel<1><<<NTOK, 256>>>(x, ln_a_g, ln_a_b, nullptr, a);

    // 2) fused q,k,v projections -> bf16 outputs
    dim3 gQKV(DDIM/128, NTOK/128, 3);
    bgemm_k<false,false,false,false,true,true><<<gQKV, 256, GSMEM>>>(
        NTOK, DDIM, DDIM, a, DDIM, bwq, bq, nullptr, (float*)qb, DDIM, nullptr, nullptr,
        bwk, bk, (float*)kb, bwv, bv, (float*)vb);

    // 3) tensor-core flash attention (causal), ctx bf16
    attn_tc_kernel<<<dim3(SS/64, HH, BB), 128>>>(qb, kb, vb, ctx);

    // 4) xa = x + ctx @ wo + bo
    dim3 gO(DDIM/128, NTOK/128, 1);
    bgemm_k<false,false,false,true,false,false><<<gO, 256, GSMEM>>>(
        NTOK, DDIM, DDIM, ctx, DDIM, bwo, bo, x, xa, DDIM, nullptr, nullptr,
        nullptr, nullptr, nullptr, nullptr, nullptr, nullptr);

    // 5) h = ln_ff(xa) (f32) + hr (bf16)
    ln_kernel<2><<<NTOK, 256>>>(xa, ln_f_g, ln_f_b, h, hrb);

    // 6) gate: top-2 per token + per-expert pair lists
    zero_cnt_kernel<<<1, 32>>>(cnt);
    gate_kernel<<<NTOK/8, 256>>>(h, gate_w, gate_b, sc, cnt, list);

    // 7) expert GEMM1: y1[pair] = bf16(relu(hr[token] @ w1[e] + b1[e]))
    bgemm_k<true,false,true,false,true,false><<<dim3(HID/128, CAP/128, EE), 256, GSMEM>>>(
        CAP, HID, DDIM, hrb, DDIM, bw1, b1, nullptr, (float*)y1, HID, list, cnt,
        nullptr, nullptr, nullptr, nullptr, nullptr, nullptr);

    // 8) expert GEMM2: o2[pair] = y1[pair] @ w2[e] + b2[e]
    bgemm_k<true,true,false,false,false,false><<<dim3(DDIM/128, CAP/128, EE), 256, GSMEM>>>(
        CAP, DDIM, HID, y1, HID, bw2, b2, nullptr, o2, DDIM, list, cnt,
        nullptr, nullptr, nullptr, nullptr, nullptr, nullptr);

    // 9) combine + post-LN + final residual
    combine_kernel<<<NTOK, 256>>>(h, o2, sc, xa, moe_g, moe_b, out);
}